// round 1
// baseline (speedup 1.0000x reference)
#include <cuda_runtime.h>

// ---------------- problem constants ----------------
#define NGEN  4
#define NSYM  100
#define NST   8      // C
// level offsets into x (cumsum of 8*4^l)
#define OFF0 0
#define OFF1 8
#define OFF2 40
#define OFF3 168
#define OFF4 680
#define OFF5 2728
#define OFF6 10920
#define OFF7 43688
#define OFF8 174760
#define DIMX 699048

#define N6 32768   // nodes at level 6 (per g lane this is the K1 work count)
#define N3 512     // nodes at level 3

// ---------------- scratch (static device, no allocs) ----------------
__device__ float g_T [NGEN * 256];        // [g][j][c][d]  softmax_c(A[c,d,j,g])
__device__ float g_B [NGEN * 1200];       // [g][sym*12 + c]  softmax_m(B[c,m,g]), padded stride 12
__device__ float g_Pi[NGEN * 8];          // [g][c]
__device__ float g_beta6[(size_t)N6 * NGEN * 8];
__device__ float g_ell6 [(size_t)N6 * NGEN];
__device__ float g_beta3[(size_t)N3 * NGEN * 8];
__device__ float g_ell3 [(size_t)N3 * NGEN];

// ---------------- helpers ----------------
__device__ __forceinline__ void emload(const float* __restrict__ sB, int v, float e[8]) {
    const float4* p = reinterpret_cast<const float4*>(sB + v * 12);
    float4 a = p[0], b = p[1];
    e[0] = a.x; e[1] = a.y; e[2] = a.z; e[3] = a.w;
    e[4] = b.x; e[5] = b.y; e[6] = b.z; e[7] = b.w;
}

// m[d] = sum_c Tj[c*8+d] * r[c]
__device__ __forceinline__ void matvec8(const float* __restrict__ Tj, const float r[8], float m[8]) {
    const float4* T4 = reinterpret_cast<const float4*>(Tj);
#pragma unroll
    for (int c = 0; c < 8; ++c) {
        float4 t0 = T4[2 * c];
        float4 t1 = T4[2 * c + 1];
        float rc = r[c];
        if (c == 0) {
            m[0] = t0.x * rc; m[1] = t0.y * rc; m[2] = t0.z * rc; m[3] = t0.w * rc;
            m[4] = t1.x * rc; m[5] = t1.y * rc; m[6] = t1.z * rc; m[7] = t1.w * rc;
        } else {
            m[0] = fmaf(t0.x, rc, m[0]); m[1] = fmaf(t0.y, rc, m[1]);
            m[2] = fmaf(t0.z, rc, m[2]); m[3] = fmaf(t0.w, rc, m[3]);
            m[4] = fmaf(t1.x, rc, m[4]); m[5] = fmaf(t1.y, rc, m[5]);
            m[6] = fmaf(t1.z, rc, m[6]); m[7] = fmaf(t1.w, rc, m[7]);
        }
    }
}

__device__ __forceinline__ float sum8(const float v[8]) {
    return ((v[0] + v[1]) + (v[2] + v[3])) + ((v[4] + v[5]) + (v[6] + v[7]));
}

// ---------------- K0: softmax tables ----------------
__global__ void k_prep(const float* __restrict__ A, const float* __restrict__ Bm,
                       const float* __restrict__ Pi) {
    int t = threadIdx.x;
    if (t < 128) {
        // softmax over c (axis 0 of A) for each (d, j, g)
        int g = t & 3, j = (t >> 2) & 3, d = t >> 4;
        float v[8]; float mx = -1e30f;
#pragma unroll
        for (int c = 0; c < 8; ++c) { v[c] = A[c * 128 + d * 16 + j * 4 + g]; mx = fmaxf(mx, v[c]); }
        float s = 0.f;
#pragma unroll
        for (int c = 0; c < 8; ++c) { v[c] = expf(v[c] - mx); s += v[c]; }
        float inv = 1.f / s;
#pragma unroll
        for (int c = 0; c < 8; ++c) g_T[g * 256 + j * 64 + c * 8 + d] = v[c] * inv;
    } else if (t < 160) {
        // softmax over m for each (c, g)
        int tt = t - 128; int g = tt & 3, c = tt >> 2;
        float mx = -1e30f;
        for (int m = 0; m < NSYM; ++m) mx = fmaxf(mx, Bm[c * 400 + m * 4 + g]);
        float s = 0.f;
        for (int m = 0; m < NSYM; ++m) s += expf(Bm[c * 400 + m * 4 + g] - mx);
        float inv = 1.f / s;
        for (int m = 0; m < NSYM; ++m)
            g_B[g * 1200 + m * 12 + c] = expf(Bm[c * 400 + m * 4 + g] - mx) * inv;
    } else if (t < 164) {
        int g = t - 160;
        float v[8]; float mx = -1e30f;
#pragma unroll
        for (int c = 0; c < 8; ++c) { v[c] = Pi[c * 4 + g]; mx = fmaxf(mx, v[c]); }
        float s = 0.f;
#pragma unroll
        for (int c = 0; c < 8; ++c) { v[c] = expf(v[c] - mx); s += v[c]; }
        float inv = 1.f / s;
#pragma unroll
        for (int c = 0; c < 8; ++c) g_Pi[g * 8 + c] = v[c] * inv;
    }
}

// ---------------- K1: levels 8,7,6 ----------------
__global__ void __launch_bounds__(256) k_bottom(const int* __restrict__ x) {
    __shared__ __align__(16) float sT[256];
    __shared__ __align__(16) float sB[1200];
    int g = blockIdx.x >> 7;                      // 512 blocks, 128 per g
    for (int i = threadIdx.x; i < 256;  i += 256) sT[i] = g_T[g * 256 + i];
    for (int i = threadIdx.x; i < 1200; i += 256) sB[i] = g_B[g * 1200 + i];
    __syncthreads();

    int n6 = ((blockIdx.x & 127) << 8) + threadIdx.x;   // 0..32767

    int v6 = __ldg(&x[OFF6 + n6]);
    int4 x7 = *reinterpret_cast<const int4*>(&x[OFF7 + 4 * n6]);
    const int4* px8 = reinterpret_cast<const int4*>(&x[OFF8 + 16 * n6]);
    int4 xa = px8[0], xb = px8[1], xc = px8[2], xd = px8[3];
    int v7a[4]  = { x7.x, x7.y, x7.z, x7.w };
    int v8a[16] = { xa.x, xa.y, xa.z, xa.w, xb.x, xb.y, xb.z, xb.w,
                    xc.x, xc.y, xc.z, xc.w, xd.x, xd.y, xd.z, xd.w };

    float ell = 0.f;
    float p6[8]; emload(sB, v6, p6);
#pragma unroll
    for (int j7 = 0; j7 < 4; ++j7) {
        float p7[8]; emload(sB, v7a[j7], p7);
#pragma unroll
        for (int j8 = 0; j8 < 4; ++j8) {
            float e[8]; emload(sB, v8a[4 * j7 + j8], e);
            float nu  = sum8(e);
            ell      += __logf(nu);
            float inv = __fdividef(1.f, nu);
            float m[8]; matvec8(&sT[j8 * 64], e, m);
#pragma unroll
            for (int d = 0; d < 8; ++d) p7[d] *= m[d] * inv;
        }
        float nu7  = sum8(p7);
        ell       += __logf(nu7);
        float inv7 = __fdividef(1.f, nu7);
        float m7[8]; matvec8(&sT[j7 * 64], p7, m7);
#pragma unroll
        for (int d = 0; d < 8; ++d) p6[d] *= m7[d] * inv7;
    }
    float nu6  = sum8(p6);
    ell       += __logf(nu6);
    float inv6 = __fdividef(1.f, nu6);

    float4* ob = reinterpret_cast<float4*>(&g_beta6[((size_t)g * N6 + n6) * 8]);
    ob[0] = make_float4(p6[0] * inv6, p6[1] * inv6, p6[2] * inv6, p6[3] * inv6);
    ob[1] = make_float4(p6[4] * inv6, p6[5] * inv6, p6[6] * inv6, p6[7] * inv6);
    g_ell6[(size_t)g * N6 + n6] = ell;
}

// ---------------- K2: levels 5,4,3 ----------------
__global__ void __launch_bounds__(256) k_mid(const int* __restrict__ x) {
    __shared__ __align__(16) float sT[256];
    __shared__ __align__(16) float sB[1200];
    int g = blockIdx.x >> 1;                      // 8 blocks, 2 per g
    for (int i = threadIdx.x; i < 256;  i += 256) sT[i] = g_T[g * 256 + i];
    for (int i = threadIdx.x; i < 1200; i += 256) sB[i] = g_B[g * 1200 + i];
    __syncthreads();

    int n3 = ((blockIdx.x & 1) << 8) + threadIdx.x;  // 0..511

    float ell = 0.f;
    float p3[8]; emload(sB, __ldg(&x[OFF3 + n3]), p3);
#pragma unroll 1
    for (int j4 = 0; j4 < 4; ++j4) {
        int n4 = 4 * n3 + j4;
        float p4[8]; emload(sB, __ldg(&x[OFF4 + n4]), p4);
#pragma unroll 1
        for (int j5 = 0; j5 < 4; ++j5) {
            int n5 = 4 * n4 + j5;
            float p5[8]; emload(sB, __ldg(&x[OFF5 + n5]), p5);
#pragma unroll
            for (int j6 = 0; j6 < 4; ++j6) {
                int n6 = 4 * n5 + j6;
                const float4* bb = reinterpret_cast<const float4*>(&g_beta6[((size_t)g * N6 + n6) * 8]);
                float4 b0 = bb[0], b1 = bb[1];
                float b[8] = { b0.x, b0.y, b0.z, b0.w, b1.x, b1.y, b1.z, b1.w };
                ell += g_ell6[(size_t)g * N6 + n6];
                float m[8]; matvec8(&sT[j6 * 64], b, m);
#pragma unroll
                for (int d = 0; d < 8; ++d) p5[d] *= m[d];
            }
            float nu5  = sum8(p5);
            ell       += __logf(nu5);
            float inv5 = __fdividef(1.f, nu5);
            float m5[8]; matvec8(&sT[j5 * 64], p5, m5);
#pragma unroll
            for (int d = 0; d < 8; ++d) p4[d] *= m5[d] * inv5;
        }
        float nu4  = sum8(p4);
        ell       += __logf(nu4);
        float inv4 = __fdividef(1.f, nu4);
        float m4[8]; matvec8(&sT[j4 * 64], p4, m4);
#pragma unroll
        for (int d = 0; d < 8; ++d) p3[d] *= m4[d] * inv4;
    }
    float nu3  = sum8(p3);
    ell       += __logf(nu3);
    float inv3 = __fdividef(1.f, nu3);

    float4* ob = reinterpret_cast<float4*>(&g_beta3[((size_t)g * N3 + n3) * 8]);
    ob[0] = make_float4(p3[0] * inv3, p3[1] * inv3, p3[2] * inv3, p3[3] * inv3);
    ob[1] = make_float4(p3[4] * inv3, p3[5] * inv3, p3[6] * inv3, p3[7] * inv3);
    g_ell3[(size_t)g * N3 + n3] = ell;
}

// ---------------- K3: levels 2,1,0 + Pi combine ----------------
__global__ void __launch_bounds__(256) k_top(const int* __restrict__ x, float* __restrict__ out) {
    __shared__ __align__(16) float sT[NGEN * 256];
    __shared__ __align__(16) float sB[NGEN * 1200];
    for (int i = threadIdx.x; i < NGEN * 256;  i += 256) sT[i] = g_T[i];
    for (int i = threadIdx.x; i < NGEN * 1200; i += 256) sB[i] = g_B[i];
    __syncthreads();
    if (threadIdx.x >= 32) return;

    int g = threadIdx.x >> 3, tree = threadIdx.x & 7;
    const float* T = &sT[g * 256];
    const float* B = &sB[g * 1200];

    float ell = 0.f;
    float p0[8]; emload(B, x[OFF0 + tree], p0);
#pragma unroll 1
    for (int j1 = 0; j1 < 4; ++j1) {
        int n1 = 4 * tree + j1;
        float p1[8]; emload(B, x[OFF1 + n1], p1);
#pragma unroll 1
        for (int j2 = 0; j2 < 4; ++j2) {
            int n2 = 4 * n1 + j2;
            float p2[8]; emload(B, x[OFF2 + n2], p2);
#pragma unroll
            for (int j3 = 0; j3 < 4; ++j3) {
                int n3 = 4 * n2 + j3;
                const float4* bb = reinterpret_cast<const float4*>(&g_beta3[((size_t)g * N3 + n3) * 8]);
                float4 b0 = bb[0], b1 = bb[1];
                float b[8] = { b0.x, b0.y, b0.z, b0.w, b1.x, b1.y, b1.z, b1.w };
                ell += g_ell3[(size_t)g * N3 + n3];
                float m[8]; matvec8(&T[j3 * 64], b, m);
#pragma unroll
                for (int d = 0; d < 8; ++d) p2[d] *= m[d];
            }
            float nu2  = sum8(p2);
            ell       += __logf(nu2);
            float inv2 = __fdividef(1.f, nu2);
            float m2[8]; matvec8(&T[j2 * 64], p2, m2);
#pragma unroll
            for (int d = 0; d < 8; ++d) p1[d] *= m2[d] * inv2;
        }
        float nu1  = sum8(p1);
        ell       += __logf(nu1);
        float inv1 = __fdividef(1.f, nu1);
        float m1[8]; matvec8(&T[j1 * 64], p1, m1);
#pragma unroll
        for (int d = 0; d < 8; ++d) p0[d] *= m1[d] * inv1;
    }
    float nu0  = sum8(p0);
    ell       += __logf(nu0);
    float inv0 = __fdividef(1.f, nu0);

    float Z = 0.f;
#pragma unroll
    for (int c = 0; c < 8; ++c) Z += g_Pi[g * 8 + c] * (p0[c] * inv0);
    out[tree * NGEN + g] = __logf(Z) + ell;
}

// ---------------- launcher ----------------
extern "C" void kernel_launch(void* const* d_in, const int* in_sizes, int n_in,
                              void* d_out, int out_size) {
    const int*   x  = nullptr;
    const float* A  = nullptr;
    const float* Bm = nullptr;
    const float* Pi = nullptr;
    for (int i = 0; i < n_in; ++i) {
        switch (in_sizes[i]) {
            case DIMX: x  = (const int*)  d_in[i]; break;
            case 1024: A  = (const float*)d_in[i]; break;
            case 3200: Bm = (const float*)d_in[i]; break;
            case 32:   Pi = (const float*)d_in[i]; break;
            default: break;
        }
    }
    k_prep  <<<  1, 192>>>(A, Bm, Pi);
    k_bottom<<<512, 256>>>(x);
    k_mid   <<<  8, 256>>>(x);
    k_top   <<<  1, 256>>>(x, (float*)d_out);
}

// round 2
// speedup vs baseline: 1.7493x; 1.7493x over previous
#include <cuda_runtime.h>

// ---------------- problem constants ----------------
#define NGEN  4
#define NSYM  100
// level offsets into x (cumsum of 8*4^l)
#define OFF0 0
#define OFF1 8
#define OFF2 40
#define OFF3 168
#define OFF4 680
#define OFF5 2728
#define OFF6 10920
#define OFF7 43688
#define OFF8 174760
#define DIMX 699048

#define N6 32768
#define N4 2048
#define N2 128

// ---------------- scratch (static device, no allocs) ----------------
__device__ float g_T [NGEN * 256];        // [g][j][c][d]
__device__ float g_B [NGEN * 1200];       // [g][sym*12 + c], stride 12
__device__ float g_Pi[NGEN * 8];
__device__ float g_beta6[(size_t)N6 * NGEN * 8];
__device__ float g_ell6 [(size_t)N6 * NGEN];
__device__ float g_beta4[(size_t)N4 * NGEN * 8];
__device__ float g_ell4 [(size_t)N4 * NGEN];
__device__ float g_beta2[(size_t)N2 * NGEN * 8];
__device__ float g_ell2 [(size_t)N2 * NGEN];

// ---------------- helpers ----------------
__device__ __forceinline__ void emload(const float* __restrict__ sB, int v, float e[8]) {
    const float4* p = reinterpret_cast<const float4*>(sB + v * 12);
    float4 a = p[0], b = p[1];
    e[0] = a.x; e[1] = a.y; e[2] = a.z; e[3] = a.w;
    e[4] = b.x; e[5] = b.y; e[6] = b.z; e[7] = b.w;
}

__device__ __forceinline__ void loadT(const float* __restrict__ sTj, float Tj[64]) {
    const float4* p = reinterpret_cast<const float4*>(sTj);
#pragma unroll
    for (int i = 0; i < 16; ++i) {
        float4 t = p[i];
        Tj[4 * i + 0] = t.x; Tj[4 * i + 1] = t.y;
        Tj[4 * i + 2] = t.z; Tj[4 * i + 3] = t.w;
    }
}

// m[d] = sum_c Tj[c*8+d] * r[c]   (Tj in registers)
__device__ __forceinline__ void matvecR(const float Tj[64], const float r[8], float m[8]) {
#pragma unroll
    for (int c = 0; c < 8; ++c) {
        float rc = r[c];
#pragma unroll
        for (int d = 0; d < 8; ++d) {
            if (c == 0) m[d] = Tj[d] * rc;
            else        m[d] = fmaf(Tj[8 * c + d], rc, m[d]);
        }
    }
}

__device__ __forceinline__ float sum8(const float v[8]) {
    return ((v[0] + v[1]) + (v[2] + v[3])) + ((v[4] + v[5]) + (v[6] + v[7]));
}

// ---------------- K0: softmax tables ----------------
__global__ void __launch_bounds__(1024) k_prep(const float* __restrict__ A,
                                               const float* __restrict__ Bm,
                                               const float* __restrict__ Pi) {
    int t = threadIdx.x;
    int w = t >> 5, lane = t & 31;

    // ---- B softmax: warp per (c,g); lanes cover 100 symbols ----
    {
        int c = w >> 2, g = w & 3;
        const float* src = Bm + c * 400 + g;
        float v0 = src[(lane)      * 4];
        float v1 = src[(lane + 32) * 4];
        float v2 = src[(lane + 64) * 4];
        float v3 = (lane < 4) ? src[(lane + 96) * 4] : -1e30f;
        float mx = fmaxf(fmaxf(v0, v1), fmaxf(v2, v3));
#pragma unroll
        for (int off = 16; off >= 1; off >>= 1)
            mx = fmaxf(mx, __shfl_xor_sync(0xffffffffu, mx, off));
        float e0 = __expf(v0 - mx), e1 = __expf(v1 - mx), e2 = __expf(v2 - mx);
        float e3 = (lane < 4) ? __expf(v3 - mx) : 0.f;
        float s = e0 + e1 + e2 + e3;
#pragma unroll
        for (int off = 16; off >= 1; off >>= 1)
            s += __shfl_xor_sync(0xffffffffu, s, off);
        float inv = 1.f / s;
        float* dst = g_B + g * 1200 + c;
        dst[(lane)      * 12] = e0 * inv;
        dst[(lane + 32) * 12] = e1 * inv;
        dst[(lane + 64) * 12] = e2 * inv;
        if (lane < 4) dst[(lane + 96) * 12] = e3 * inv;
    }

    // ---- A softmax over c, per (d, j, g) ----
    if (t < 128) {
        int g = t & 3, j = (t >> 2) & 3, d = t >> 4;
        float v[8]; float mx = -1e30f;
#pragma unroll
        for (int c = 0; c < 8; ++c) { v[c] = A[c * 128 + d * 16 + j * 4 + g]; mx = fmaxf(mx, v[c]); }
        float s = 0.f;
#pragma unroll
        for (int c = 0; c < 8; ++c) { v[c] = __expf(v[c] - mx); s += v[c]; }
        float inv = 1.f / s;
#pragma unroll
        for (int c = 0; c < 8; ++c) g_T[g * 256 + j * 64 + c * 8 + d] = v[c] * inv;
    } else if (t < 132) {
        int g = t - 128;
        float v[8]; float mx = -1e30f;
#pragma unroll
        for (int c = 0; c < 8; ++c) { v[c] = Pi[c * 4 + g]; mx = fmaxf(mx, v[c]); }
        float s = 0.f;
#pragma unroll
        for (int c = 0; c < 8; ++c) { v[c] = __expf(v[c] - mx); s += v[c]; }
        float inv = 1.f / s;
#pragma unroll
        for (int c = 0; c < 8; ++c) g_Pi[g * 8 + c] = v[c] * inv;
    }
}

// ---------------- K1: levels 8,7,6 ----------------
// 1024 blocks x 128 threads; thread per (n6, g)
__global__ void __launch_bounds__(128) k_bottom(const int* __restrict__ x) {
    __shared__ __align__(16) float sT[256];
    __shared__ __align__(16) float sB[1200];
    int g = blockIdx.x >> 8;                     // 256 blocks per g
    for (int i = threadIdx.x; i < 256;  i += 128) sT[i] = g_T[g * 256 + i];
    for (int i = threadIdx.x; i < 1200; i += 128) sB[i] = g_B[g * 1200 + i];
    __syncthreads();

    int n6 = ((blockIdx.x & 255) << 7) + threadIdx.x;   // 0..32767

    int v6 = __ldg(&x[OFF6 + n6]);
    int4 x7 = *reinterpret_cast<const int4*>(&x[OFF7 + 4 * n6]);
    const int4* px8 = reinterpret_cast<const int4*>(&x[OFF8 + 16 * n6]);
    int4 xa = px8[0], xb = px8[1], xc = px8[2], xd = px8[3];
    int v7a[4]  = { x7.x, x7.y, x7.z, x7.w };
    int v8a[16] = { xa.x, xa.y, xa.z, xa.w, xb.x, xb.y, xb.z, xb.w,
                    xc.x, xc.y, xc.z, xc.w, xd.x, xd.y, xd.z, xd.w };

    float p7[4][8];
#pragma unroll
    for (int j7 = 0; j7 < 4; ++j7) emload(sB, v7a[j7], p7[j7]);

    float ell = 0.f;
    // leaf level: j8-outer so each T tile is loaded once, used for 4 matvecs
#pragma unroll
    for (int j8 = 0; j8 < 4; ++j8) {
        float Tj[64]; loadT(&sT[j8 * 64], Tj);
#pragma unroll
        for (int j7 = 0; j7 < 4; ++j7) {
            float e[8]; emload(sB, v8a[4 * j7 + j8], e);
            float nu  = sum8(e);
            ell      += __logf(nu);
            float inv = __fdividef(1.f, nu);
            float m[8]; matvecR(Tj, e, m);
#pragma unroll
            for (int d = 0; d < 8; ++d) p7[j7][d] *= m[d] * inv;
        }
    }

    float p6[8]; emload(sB, v6, p6);
#pragma unroll
    for (int j7 = 0; j7 < 4; ++j7) {
        float nu  = sum8(p7[j7]);
        ell      += __logf(nu);
        float inv = __fdividef(1.f, nu);
        float Tj[64]; loadT(&sT[j7 * 64], Tj);
        float m[8]; matvecR(Tj, p7[j7], m);
#pragma unroll
        for (int d = 0; d < 8; ++d) p6[d] *= m[d] * inv;
    }
    float nu6  = sum8(p6);
    ell       += __logf(nu6);
    float inv6 = __fdividef(1.f, nu6);

    float4* ob = reinterpret_cast<float4*>(&g_beta6[((size_t)g * N6 + n6) * 8]);
    ob[0] = make_float4(p6[0] * inv6, p6[1] * inv6, p6[2] * inv6, p6[3] * inv6);
    ob[1] = make_float4(p6[4] * inv6, p6[5] * inv6, p6[6] * inv6, p6[7] * inv6);
    g_ell6[(size_t)g * N6 + n6] = ell;
}

// ---------------- K2: levels 5,4 (consume beta6, produce beta4) ----------------
// 32 blocks x 256 threads; thread per (n4, g)
__global__ void __launch_bounds__(256) k_mid54(const int* __restrict__ x) {
    __shared__ __align__(16) float sT[256];
    __shared__ __align__(16) float sB[1200];
    int g = blockIdx.x >> 3;                     // 8 blocks per g
    for (int i = threadIdx.x; i < 256;  i += 256) sT[i] = g_T[g * 256 + i];
    for (int i = threadIdx.x; i < 1200; i += 256) sB[i] = g_B[g * 1200 + i];
    __syncthreads();

    int n4 = ((blockIdx.x & 7) << 8) + threadIdx.x;   // 0..2047

    int4 x5 = *reinterpret_cast<const int4*>(&x[OFF5 + 4 * n4]);
    int v5a[4] = { x5.x, x5.y, x5.z, x5.w };

    float p5[4][8];
#pragma unroll
    for (int j5 = 0; j5 < 4; ++j5) emload(sB, v5a[j5], p5[j5]);

    float ell = 0.f;
#pragma unroll
    for (int j6 = 0; j6 < 4; ++j6) {
        float Tj[64]; loadT(&sT[j6 * 64], Tj);
#pragma unroll
        for (int j5 = 0; j5 < 4; ++j5) {
            int n6 = 16 * n4 + 4 * j5 + j6;
            const float4* bb = reinterpret_cast<const float4*>(&g_beta6[((size_t)g * N6 + n6) * 8]);
            float4 b0 = bb[0], b1 = bb[1];
            float b[8] = { b0.x, b0.y, b0.z, b0.w, b1.x, b1.y, b1.z, b1.w };
            ell += g_ell6[(size_t)g * N6 + n6];
            float m[8]; matvecR(Tj, b, m);
#pragma unroll
            for (int d = 0; d < 8; ++d) p5[j5][d] *= m[d];
        }
    }

    float p4[8]; emload(sB, __ldg(&x[OFF4 + n4]), p4);
#pragma unroll
    for (int j5 = 0; j5 < 4; ++j5) {
        float nu  = sum8(p5[j5]);
        ell      += __logf(nu);
        float inv = __fdividef(1.f, nu);
        float Tj[64]; loadT(&sT[j5 * 64], Tj);
        float m[8]; matvecR(Tj, p5[j5], m);
#pragma unroll
        for (int d = 0; d < 8; ++d) p4[d] *= m[d] * inv;
    }
    float nu4  = sum8(p4);
    ell       += __logf(nu4);
    float inv4 = __fdividef(1.f, nu4);

    float4* ob = reinterpret_cast<float4*>(&g_beta4[((size_t)g * N4 + n4) * 8]);
    ob[0] = make_float4(p4[0] * inv4, p4[1] * inv4, p4[2] * inv4, p4[3] * inv4);
    ob[1] = make_float4(p4[4] * inv4, p4[5] * inv4, p4[6] * inv4, p4[7] * inv4);
    g_ell4[(size_t)g * N4 + n4] = ell;
}

// ---------------- K3: levels 3,2 (consume beta4, produce beta2) ----------------
// 4 blocks x 128 threads; block = g, thread = n2
__global__ void __launch_bounds__(128) k_mid32(const int* __restrict__ x) {
    __shared__ __align__(16) float sT[256];
    __shared__ __align__(16) float sB[1200];
    int g = blockIdx.x;
    for (int i = threadIdx.x; i < 256;  i += 128) sT[i] = g_T[g * 256 + i];
    for (int i = threadIdx.x; i < 1200; i += 128) sB[i] = g_B[g * 1200 + i];
    __syncthreads();

    int n2 = threadIdx.x;   // 0..127

    int4 x3 = *reinterpret_cast<const int4*>(&x[OFF3 + 4 * n2]);
    int v3a[4] = { x3.x, x3.y, x3.z, x3.w };

    float p3[4][8];
#pragma unroll
    for (int j3 = 0; j3 < 4; ++j3) emload(sB, v3a[j3], p3[j3]);

    float ell = 0.f;
#pragma unroll
    for (int j4 = 0; j4 < 4; ++j4) {
        float Tj[64]; loadT(&sT[j4 * 64], Tj);
#pragma unroll
        for (int j3 = 0; j3 < 4; ++j3) {
            int n4 = 16 * n2 + 4 * j3 + j4;
            const float4* bb = reinterpret_cast<const float4*>(&g_beta4[((size_t)g * N4 + n4) * 8]);
            float4 b0 = bb[0], b1 = bb[1];
            float b[8] = { b0.x, b0.y, b0.z, b0.w, b1.x, b1.y, b1.z, b1.w };
            ell += g_ell4[(size_t)g * N4 + n4];
            float m[8]; matvecR(Tj, b, m);
#pragma unroll
            for (int d = 0; d < 8; ++d) p3[j3][d] *= m[d];
        }
    }

    float p2[8]; emload(sB, __ldg(&x[OFF2 + n2]), p2);
#pragma unroll
    for (int j3 = 0; j3 < 4; ++j3) {
        float nu  = sum8(p3[j3]);
        ell      += __logf(nu);
        float inv = __fdividef(1.f, nu);
        float Tj[64]; loadT(&sT[j3 * 64], Tj);
        float m[8]; matvecR(Tj, p3[j3], m);
#pragma unroll
        for (int d = 0; d < 8; ++d) p2[d] *= m[d] * inv;
    }
    float nu2  = sum8(p2);
    ell       += __logf(nu2);
    float inv2 = __fdividef(1.f, nu2);

    float4* ob = reinterpret_cast<float4*>(&g_beta2[((size_t)g * N2 + n2) * 8]);
    ob[0] = make_float4(p2[0] * inv2, p2[1] * inv2, p2[2] * inv2, p2[3] * inv2);
    ob[1] = make_float4(p2[4] * inv2, p2[5] * inv2, p2[6] * inv2, p2[7] * inv2);
    g_ell2[(size_t)g * N2 + n2] = ell;
}

// ---------------- K4: levels 1,0 + Pi combine ----------------
__global__ void __launch_bounds__(128) k_top2(const int* __restrict__ x, float* __restrict__ out) {
    __shared__ __align__(16) float sT[NGEN * 256];
    __shared__ __align__(16) float sB[NGEN * 1200];
    for (int i = threadIdx.x; i < NGEN * 256;  i += 128) sT[i] = g_T[i];
    for (int i = threadIdx.x; i < NGEN * 1200; i += 128) sB[i] = g_B[i];
    __syncthreads();
    if (threadIdx.x >= 32) return;

    int g = threadIdx.x >> 3, tree = threadIdx.x & 7;
    const float* T = &sT[g * 256];
    const float* B = &sB[g * 1200];

    float p1[4][8];
#pragma unroll
    for (int j1 = 0; j1 < 4; ++j1) emload(B, x[OFF1 + 4 * tree + j1], p1[j1]);

    float ell = 0.f;
#pragma unroll
    for (int j2 = 0; j2 < 4; ++j2) {
        float Tj[64]; loadT(&T[j2 * 64], Tj);
#pragma unroll
        for (int j1 = 0; j1 < 4; ++j1) {
            int n2 = 16 * tree + 4 * j1 + j2;
            const float4* bb = reinterpret_cast<const float4*>(&g_beta2[((size_t)g * N2 + n2) * 8]);
            float4 b0 = bb[0], b1 = bb[1];
            float b[8] = { b0.x, b0.y, b0.z, b0.w, b1.x, b1.y, b1.z, b1.w };
            ell += g_ell2[(size_t)g * N2 + n2];
            float m[8]; matvecR(Tj, b, m);
#pragma unroll
            for (int d = 0; d < 8; ++d) p1[j1][d] *= m[d];
        }
    }

    float p0[8]; emload(B, x[OFF0 + tree], p0);
#pragma unroll
    for (int j1 = 0; j1 < 4; ++j1) {
        float nu  = sum8(p1[j1]);
        ell      += __logf(nu);
        float inv = __fdividef(1.f, nu);
        float Tj[64]; loadT(&T[j1 * 64], Tj);
        float m[8]; matvecR(Tj, p1[j1], m);
#pragma unroll
        for (int d = 0; d < 8; ++d) p0[d] *= m[d] * inv;
    }
    float nu0  = sum8(p0);
    ell       += __logf(nu0);
    float inv0 = __fdividef(1.f, nu0);

    float Z = 0.f;
#pragma unroll
    for (int c = 0; c < 8; ++c) Z += g_Pi[g * 8 + c] * (p0[c] * inv0);
    out[tree * NGEN + g] = __logf(Z) + ell;
}

// ---------------- launcher ----------------
extern "C" void kernel_launch(void* const* d_in, const int* in_sizes, int n_in,
                              void* d_out, int out_size) {
    const int*   x  = nullptr;
    const float* A  = nullptr;
    const float* Bm = nullptr;
    const float* Pi = nullptr;
    for (int i = 0; i < n_in; ++i) {
        switch (in_sizes[i]) {
            case DIMX: x  = (const int*)  d_in[i]; break;
            case 1024: A  = (const float*)d_in[i]; break;
            case 3200: Bm = (const float*)d_in[i]; break;
            case 32:   Pi = (const float*)d_in[i]; break;
            default: break;
        }
    }
    k_prep  <<<   1, 1024>>>(A, Bm, Pi);
    k_bottom<<<1024,  128>>>(x);
    k_mid54 <<<  32,  256>>>(x);
    k_mid32 <<<   4,  128>>>(x);
    k_top2  <<<   1,  128>>>(x, (float*)d_out);
}

// round 3
// speedup vs baseline: 1.9473x; 1.1132x over previous
#include <cuda_runtime.h>

// ---------------- problem constants ----------------
#define NGEN  4
#define NSYM  100
// level offsets into x (cumsum of 8*4^l)
#define OFF0 0
#define OFF1 8
#define OFF2 40
#define OFF3 168
#define OFF4 680
#define OFF5 2728
#define OFF6 10920
#define OFF7 43688
#define OFF8 174760
#define DIMX 699048

#define N6 32768
#define N4 2048
#define N2 128

// ---------------- scratch (static device, no allocs) ----------------
__device__ float g_T [NGEN * 256];          // [g][j][c][d]
__device__ float g_B [NGEN * 1200];         // [g][sym*12 + c]
__device__ float g_U [NGEN * 4800];         // [g][(j*100+v)*12 + d]  leaf-lift table (normalized)
__device__ float g_LN[NGEN * NSYM];         // [g][v]  log(sum_c B[v][c])
__device__ float g_Pi[NGEN * 8];
__device__ float g_beta6[(size_t)N6 * NGEN * 8];
__device__ float g_ell6 [(size_t)N6 * NGEN];
__device__ float g_beta4[(size_t)N4 * NGEN * 8];
__device__ float g_ell4 [(size_t)N4 * NGEN];

// ---------------- helpers ----------------
__device__ __forceinline__ void emload(const float* __restrict__ sB, int v, float e[8]) {
    const float4* p = reinterpret_cast<const float4*>(sB + v * 12);
    float4 a = p[0], b = p[1];
    e[0] = a.x; e[1] = a.y; e[2] = a.z; e[3] = a.w;
    e[4] = b.x; e[5] = b.y; e[6] = b.z; e[7] = b.w;
}

// m[d] = sum_c Tj[c*8+d] * r[c], T read from shared (broadcast across warp)
__device__ __forceinline__ void matvecS(const float* __restrict__ sTj, const float r[8], float m[8]) {
    const float4* T4 = reinterpret_cast<const float4*>(sTj);
#pragma unroll
    for (int c = 0; c < 8; ++c) {
        float4 t0 = T4[2 * c];
        float4 t1 = T4[2 * c + 1];
        float rc = r[c];
        if (c == 0) {
            m[0] = t0.x * rc; m[1] = t0.y * rc; m[2] = t0.z * rc; m[3] = t0.w * rc;
            m[4] = t1.x * rc; m[5] = t1.y * rc; m[6] = t1.z * rc; m[7] = t1.w * rc;
        } else {
            m[0] = fmaf(t0.x, rc, m[0]); m[1] = fmaf(t0.y, rc, m[1]);
            m[2] = fmaf(t0.z, rc, m[2]); m[3] = fmaf(t0.w, rc, m[3]);
            m[4] = fmaf(t1.x, rc, m[4]); m[5] = fmaf(t1.y, rc, m[5]);
            m[6] = fmaf(t1.z, rc, m[6]); m[7] = fmaf(t1.w, rc, m[7]);
        }
    }
}

__device__ __forceinline__ float sum8(const float v[8]) {
    return ((v[0] + v[1]) + (v[2] + v[3])) + ((v[4] + v[5]) + (v[6] + v[7]));
}

// ---------------- K0: softmax tables + leaf-lift table ----------------
__global__ void __launch_bounds__(1024) k_prep(const float* __restrict__ A,
                                               const float* __restrict__ Bm,
                                               const float* __restrict__ Pi) {
    int t = threadIdx.x;
    int w = t >> 5, lane = t & 31;

    // ---- B softmax: warp per (c,g); lanes cover 100 symbols ----
    {
        int c = w >> 2, g = w & 3;
        const float* src = Bm + c * 400 + g;
        float v0 = src[(lane)      * 4];
        float v1 = src[(lane + 32) * 4];
        float v2 = src[(lane + 64) * 4];
        float v3 = (lane < 4) ? src[(lane + 96) * 4] : -1e30f;
        float mx = fmaxf(fmaxf(v0, v1), fmaxf(v2, v3));
#pragma unroll
        for (int off = 16; off >= 1; off >>= 1)
            mx = fmaxf(mx, __shfl_xor_sync(0xffffffffu, mx, off));
        float e0 = __expf(v0 - mx), e1 = __expf(v1 - mx), e2 = __expf(v2 - mx);
        float e3 = (lane < 4) ? __expf(v3 - mx) : 0.f;
        float s = e0 + e1 + e2 + e3;
#pragma unroll
        for (int off = 16; off >= 1; off >>= 1)
            s += __shfl_xor_sync(0xffffffffu, s, off);
        float inv = 1.f / s;
        float* dst = g_B + g * 1200 + c;
        dst[(lane)      * 12] = e0 * inv;
        dst[(lane + 32) * 12] = e1 * inv;
        dst[(lane + 64) * 12] = e2 * inv;
        if (lane < 4) dst[(lane + 96) * 12] = e3 * inv;
    }

    // ---- A softmax over c, per (d, j, g) ----
    if (t < 128) {
        int g = t & 3, j = (t >> 2) & 3, d = t >> 4;
        float v[8]; float mx = -1e30f;
#pragma unroll
        for (int c = 0; c < 8; ++c) { v[c] = A[c * 128 + d * 16 + j * 4 + g]; mx = fmaxf(mx, v[c]); }
        float s = 0.f;
#pragma unroll
        for (int c = 0; c < 8; ++c) { v[c] = __expf(v[c] - mx); s += v[c]; }
        float inv = 1.f / s;
#pragma unroll
        for (int c = 0; c < 8; ++c) g_T[g * 256 + j * 64 + c * 8 + d] = v[c] * inv;
    } else if (t < 132) {
        int g = t - 128;
        float v[8]; float mx = -1e30f;
#pragma unroll
        for (int c = 0; c < 8; ++c) { v[c] = Pi[c * 4 + g]; mx = fmaxf(mx, v[c]); }
        float s = 0.f;
#pragma unroll
        for (int c = 0; c < 8; ++c) { v[c] = __expf(v[c] - mx); s += v[c]; }
        float inv = 1.f / s;
#pragma unroll
        for (int c = 0; c < 8; ++c) g_Pi[g * 8 + c] = v[c] * inv;
    }

    __syncthreads();

    // ---- phase 2: leaf-lift table U and LN ----
    // jobs: (g, j, v), 1600 total
    for (int job = t; job < 1600; job += 1024) {
        int v = job % 100;
        int j = (job / 100) & 3;
        int g = job / 400;
        float e[8];
#pragma unroll
        for (int c = 0; c < 8; ++c) e[c] = g_B[g * 1200 + v * 12 + c];
        float s = sum8(e);
        float inv = 1.f / s;
        const float* T = &g_T[g * 256 + j * 64];
        float* dst = &g_U[g * 4800 + (j * 100 + v) * 12];
#pragma unroll
        for (int d = 0; d < 8; ++d) {
            float acc = 0.f;
#pragma unroll
            for (int c = 0; c < 8; ++c) acc = fmaf(T[c * 8 + d], e[c], acc);
            dst[d] = acc * inv;
        }
        if (j == 0) g_LN[g * NSYM + v] = __logf(s);
    }
}

// ---------------- K1: levels 8,7,6 ----------------
// 256 blocks x 512 threads; thread per (n6, g)
__global__ void __launch_bounds__(512) k_bottom(const int* __restrict__ x) {
    __shared__ __align__(16) float sT[256];
    __shared__ __align__(16) float sB[1200];
    __shared__ __align__(16) float sU[4800];
    __shared__ float sLN[NSYM];
    int g = blockIdx.x >> 6;                     // 64 blocks per g
    for (int i = threadIdx.x; i < 256;  i += 512) sT[i] = g_T[g * 256 + i];
    for (int i = threadIdx.x; i < 1200; i += 512) sB[i] = g_B[g * 1200 + i];
    for (int i = threadIdx.x; i < 4800; i += 512) sU[i] = g_U[g * 4800 + i];
    if (threadIdx.x < NSYM) sLN[threadIdx.x] = g_LN[g * NSYM + threadIdx.x];
    __syncthreads();

    int n6 = ((blockIdx.x & 63) << 9) + threadIdx.x;   // 0..32767

    int v6 = __ldg(&x[OFF6 + n6]);
    int4 x7 = *reinterpret_cast<const int4*>(&x[OFF7 + 4 * n6]);
    const int4* px8 = reinterpret_cast<const int4*>(&x[OFF8 + 16 * n6]);
    int4 xa = px8[0], xb = px8[1], xc = px8[2], xd = px8[3];
    int v7a[4]  = { x7.x, x7.y, x7.z, x7.w };
    int v8a[16] = { xa.x, xa.y, xa.z, xa.w, xb.x, xb.y, xb.z, xb.w,
                    xc.x, xc.y, xc.z, xc.w, xd.x, xd.y, xd.z, xd.w };

    float p6[8]; emload(sB, v6, p6);
    float ell = 0.f;
#pragma unroll 1
    for (int j7 = 0; j7 < 4; ++j7) {
        float p[8]; emload(sB, v7a[j7], p);
#pragma unroll
        for (int j8 = 0; j8 < 4; ++j8) {
            int v = v8a[4 * j7 + j8];
            const float4* u = reinterpret_cast<const float4*>(sU + (j8 * 100 + v) * 12);
            float4 ua = u[0], ub = u[1];
            p[0] *= ua.x; p[1] *= ua.y; p[2] *= ua.z; p[3] *= ua.w;
            p[4] *= ub.x; p[5] *= ub.y; p[6] *= ub.z; p[7] *= ub.w;
            ell += sLN[v];
        }
        float nu  = sum8(p);
        ell      += __logf(nu);
        float inv = __fdividef(1.f, nu);
        float m[8]; matvecS(&sT[j7 * 64], p, m);
#pragma unroll
        for (int d = 0; d < 8; ++d) p6[d] *= m[d] * inv;
    }
    float nu6  = sum8(p6);
    ell       += __logf(nu6);
    float inv6 = __fdividef(1.f, nu6);

    float4* ob = reinterpret_cast<float4*>(&g_beta6[((size_t)g * N6 + n6) * 8]);
    ob[0] = make_float4(p6[0] * inv6, p6[1] * inv6, p6[2] * inv6, p6[3] * inv6);
    ob[1] = make_float4(p6[4] * inv6, p6[5] * inv6, p6[6] * inv6, p6[7] * inv6);
    g_ell6[(size_t)g * N6 + n6] = ell;
}

// ---------------- K2: levels 5,4 ----------------
// 64 blocks x 128 threads; thread per (n4, g)
__global__ void __launch_bounds__(128) k_mid54(const int* __restrict__ x) {
    __shared__ __align__(16) float sT[256];
    __shared__ __align__(16) float sB[1200];
    int g = blockIdx.x >> 4;                     // 16 blocks per g
    for (int i = threadIdx.x; i < 256;  i += 128) sT[i] = g_T[g * 256 + i];
    for (int i = threadIdx.x; i < 1200; i += 128) sB[i] = g_B[g * 1200 + i];
    __syncthreads();

    int n4 = ((blockIdx.x & 15) << 7) + threadIdx.x;   // 0..2047

    int4 x5 = *reinterpret_cast<const int4*>(&x[OFF5 + 4 * n4]);
    int v5a[4] = { x5.x, x5.y, x5.z, x5.w };

    float p4[8]; emload(sB, __ldg(&x[OFF4 + n4]), p4);
    float ell = 0.f;
#pragma unroll 1
    for (int j5 = 0; j5 < 4; ++j5) {
        float p[8]; emload(sB, v5a[j5], p);
#pragma unroll
        for (int j6 = 0; j6 < 4; ++j6) {
            int n6 = 16 * n4 + 4 * j5 + j6;
            const float4* bb = reinterpret_cast<const float4*>(&g_beta6[((size_t)g * N6 + n6) * 8]);
            float4 b0 = bb[0], b1 = bb[1];
            float b[8] = { b0.x, b0.y, b0.z, b0.w, b1.x, b1.y, b1.z, b1.w };
            ell += g_ell6[(size_t)g * N6 + n6];
            float m[8]; matvecS(&sT[j6 * 64], b, m);
#pragma unroll
            for (int d = 0; d < 8; ++d) p[d] *= m[d];
        }
        float nu  = sum8(p);
        ell      += __logf(nu);
        float inv = __fdividef(1.f, nu);
        float m[8]; matvecS(&sT[j5 * 64], p, m);
#pragma unroll
        for (int d = 0; d < 8; ++d) p4[d] *= m[d] * inv;
    }
    float nu4  = sum8(p4);
    ell       += __logf(nu4);
    float inv4 = __fdividef(1.f, nu4);

    float4* ob = reinterpret_cast<float4*>(&g_beta4[((size_t)g * N4 + n4) * 8]);
    ob[0] = make_float4(p4[0] * inv4, p4[1] * inv4, p4[2] * inv4, p4[3] * inv4);
    ob[1] = make_float4(p4[4] * inv4, p4[5] * inv4, p4[6] * inv4, p4[7] * inv4);
    g_ell4[(size_t)g * N4 + n4] = ell;
}

// ---------------- K3: levels 3,2,1,0 + Pi combine (block per g) ----------------
__global__ void __launch_bounds__(128) k_tail(const int* __restrict__ x, float* __restrict__ out) {
    __shared__ __align__(16) float sT[256];
    __shared__ __align__(16) float sB[1200];
    __shared__ __align__(16) float sBeta2[N2 * 8];
    __shared__ float sEll2[N2];
    int g = blockIdx.x;
    for (int i = threadIdx.x; i < 256;  i += 128) sT[i] = g_T[g * 256 + i];
    for (int i = threadIdx.x; i < 1200; i += 128) sB[i] = g_B[g * 1200 + i];
    __syncthreads();

    // ---- stage A: levels 3,2 ; thread per n2 ----
    {
        int n2 = threadIdx.x;   // 0..127
        int4 x3 = *reinterpret_cast<const int4*>(&x[OFF3 + 4 * n2]);
        int v3a[4] = { x3.x, x3.y, x3.z, x3.w };

        float p2[8]; emload(sB, __ldg(&x[OFF2 + n2]), p2);
        float ell = 0.f;
#pragma unroll 1
        for (int j3 = 0; j3 < 4; ++j3) {
            float p[8]; emload(sB, v3a[j3], p);
#pragma unroll
            for (int j4 = 0; j4 < 4; ++j4) {
                int n4 = 16 * n2 + 4 * j3 + j4;
                const float4* bb = reinterpret_cast<const float4*>(&g_beta4[((size_t)g * N4 + n4) * 8]);
                float4 b0 = bb[0], b1 = bb[1];
                float b[8] = { b0.x, b0.y, b0.z, b0.w, b1.x, b1.y, b1.z, b1.w };
                ell += g_ell4[(size_t)g * N4 + n4];
                float m[8]; matvecS(&sT[j4 * 64], b, m);
#pragma unroll
                for (int d = 0; d < 8; ++d) p[d] *= m[d];
            }
            float nu  = sum8(p);
            ell      += __logf(nu);
            float inv = __fdividef(1.f, nu);
            float m[8]; matvecS(&sT[j3 * 64], p, m);
#pragma unroll
            for (int d = 0; d < 8; ++d) p2[d] *= m[d] * inv;
        }
        float nu2  = sum8(p2);
        ell       += __logf(nu2);
        float inv2 = __fdividef(1.f, nu2);
#pragma unroll
        for (int d = 0; d < 8; ++d) sBeta2[n2 * 8 + d] = p2[d] * inv2;
        sEll2[n2] = ell;
    }
    __syncthreads();

    // ---- stage B: levels 1,0 + Pi ; thread per tree ----
    if (threadIdx.x < 8) {
        int tree = threadIdx.x;
        float p0[8]; emload(sB, x[OFF0 + tree], p0);
        float ell = 0.f;
#pragma unroll 1
        for (int j1 = 0; j1 < 4; ++j1) {
            float p[8]; emload(sB, x[OFF1 + 4 * tree + j1], p);
#pragma unroll
            for (int j2 = 0; j2 < 4; ++j2) {
                int n2 = 16 * tree + 4 * j1 + j2;
                float b[8];
#pragma unroll
                for (int d = 0; d < 8; ++d) b[d] = sBeta2[n2 * 8 + d];
                ell += sEll2[n2];
                float m[8]; matvecS(&sT[j2 * 64], b, m);
#pragma unroll
                for (int d = 0; d < 8; ++d) p[d] *= m[d];
            }
            float nu  = sum8(p);
            ell      += __logf(nu);
            float inv = __fdividef(1.f, nu);
            float m[8]; matvecS(&sT[j1 * 64], p, m);
#pragma unroll
            for (int d = 0; d < 8; ++d) p0[d] *= m[d] * inv;
        }
        float nu0  = sum8(p0);
        ell       += __logf(nu0);
        float inv0 = __fdividef(1.f, nu0);

        float Z = 0.f;
#pragma unroll
        for (int c = 0; c < 8; ++c) Z += g_Pi[g * 8 + c] * (p0[c] * inv0);
        out[tree * NGEN + g] = __logf(Z) + ell;
    }
}

// ---------------- launcher ----------------
extern "C" void kernel_launch(void* const* d_in, const int* in_sizes, int n_in,
                              void* d_out, int out_size) {
    const int*   x  = nullptr;
    const float* A  = nullptr;
    const float* Bm = nullptr;
    const float* Pi = nullptr;
    for (int i = 0; i < n_in; ++i) {
        switch (in_sizes[i]) {
            case DIMX: x  = (const int*)  d_in[i]; break;
            case 1024: A  = (const float*)d_in[i]; break;
            case 3200: Bm = (const float*)d_in[i]; break;
            case 32:   Pi = (const float*)d_in[i]; break;
            default: break;
        }
    }
    k_prep  <<<  1, 1024>>>(A, Bm, Pi);
    k_bottom<<<256,  512>>>(x);
    k_mid54 <<< 64,  128>>>(x);
    k_tail  <<<  4,  128>>>(x, (float*)d_out);
}

// round 4
// speedup vs baseline: 2.3050x; 1.1837x over previous
#include <cuda_runtime.h>

// ---------------- problem constants ----------------
#define NGEN  4
#define NSYM  100
// level offsets into x (cumsum of 8*4^l)
#define OFF0 0
#define OFF1 8
#define OFF2 40
#define OFF3 168
#define OFF4 680
#define OFF5 2728
#define OFF6 10920
#define OFF7 43688
#define OFF8 174760
#define DIMX 699048

#define N6 32768
#define N4 2048
#define N2 128

// ---------------- scratch (static device, no allocs) ----------------
__device__ float g_T [NGEN * 256];          // [g][j][c][d]
__device__ float g_B [NGEN * 1200];         // [g][sym*12 + c]
__device__ float g_U [NGEN * 4800];         // [g][(j*100+v)*12 + d]  leaf-lift (normalized)
__device__ float g_LN[NGEN * NSYM];         // [g][v]  log(sum_c B[v][c])
__device__ float g_Pi[NGEN * 8];
__device__ float g_beta6[(size_t)N6 * NGEN * 8];
__device__ float g_ell6 [(size_t)N6 * NGEN];
__device__ float g_beta4[(size_t)N4 * NGEN * 8];
__device__ float g_ell4 [(size_t)N4 * NGEN];
__device__ float g_beta2[(size_t)N2 * NGEN * 8];
__device__ float g_ell2 [(size_t)N2 * NGEN];

// ---------------- scalar helpers (k_bottom) ----------------
__device__ __forceinline__ void emload(const float* __restrict__ sB, int v, float e[8]) {
    const float4* p = reinterpret_cast<const float4*>(sB + v * 12);
    float4 a = p[0], b = p[1];
    e[0] = a.x; e[1] = a.y; e[2] = a.z; e[3] = a.w;
    e[4] = b.x; e[5] = b.y; e[6] = b.z; e[7] = b.w;
}

__device__ __forceinline__ void matvecS(const float* __restrict__ sTj, const float r[8], float m[8]) {
    const float4* T4 = reinterpret_cast<const float4*>(sTj);
#pragma unroll
    for (int c = 0; c < 8; ++c) {
        float4 t0 = T4[2 * c];
        float4 t1 = T4[2 * c + 1];
        float rc = r[c];
        if (c == 0) {
            m[0] = t0.x * rc; m[1] = t0.y * rc; m[2] = t0.z * rc; m[3] = t0.w * rc;
            m[4] = t1.x * rc; m[5] = t1.y * rc; m[6] = t1.z * rc; m[7] = t1.w * rc;
        } else {
            m[0] = fmaf(t0.x, rc, m[0]); m[1] = fmaf(t0.y, rc, m[1]);
            m[2] = fmaf(t0.z, rc, m[2]); m[3] = fmaf(t0.w, rc, m[3]);
            m[4] = fmaf(t1.x, rc, m[4]); m[5] = fmaf(t1.y, rc, m[5]);
            m[6] = fmaf(t1.z, rc, m[6]); m[7] = fmaf(t1.w, rc, m[7]);
        }
    }
}

__device__ __forceinline__ float sum8(const float v[8]) {
    return ((v[0] + v[1]) + (v[2] + v[3])) + ((v[4] + v[5]) + (v[6] + v[7]));
}

// ---------------- warp-distributed helpers ----------------
// vector of 8 states distributed over a group of 8 lanes (lane holds component d)
__device__ __forceinline__ float groupSum8(float v) {
    v += __shfl_xor_sync(0xffffffffu, v, 4, 8);
    v += __shfl_xor_sync(0xffffffffu, v, 2, 8);
    v += __shfl_xor_sync(0xffffffffu, v, 1, 8);
    return v;
}

// m_d = sum_c T[j][c][d] * bhat_c  (bhat distributed in this group)
__device__ __forceinline__ float groupMatvec(const float* __restrict__ sTj, float bhat, int d) {
    float m = 0.f;
#pragma unroll
    for (int c = 0; c < 8; ++c) {
        float bc = __shfl_sync(0xffffffffu, bhat, c, 8);
        m = fmaf(sTj[c * 8 + d], bc, m);
    }
    return m;
}

// ---------------- K0: softmax tables + leaf-lift table ----------------
__global__ void __launch_bounds__(1024) k_prep(const float* __restrict__ A,
                                               const float* __restrict__ Bm,
                                               const float* __restrict__ Pi) {
    int t = threadIdx.x;
    int w = t >> 5, lane = t & 31;

    // ---- B softmax: warp per (c,g); lanes cover 100 symbols ----
    {
        int c = w >> 2, g = w & 3;
        const float* src = Bm + c * 400 + g;
        float v0 = src[(lane)      * 4];
        float v1 = src[(lane + 32) * 4];
        float v2 = src[(lane + 64) * 4];
        float v3 = (lane < 4) ? src[(lane + 96) * 4] : -1e30f;
        float mx = fmaxf(fmaxf(v0, v1), fmaxf(v2, v3));
#pragma unroll
        for (int off = 16; off >= 1; off >>= 1)
            mx = fmaxf(mx, __shfl_xor_sync(0xffffffffu, mx, off));
        float e0 = __expf(v0 - mx), e1 = __expf(v1 - mx), e2 = __expf(v2 - mx);
        float e3 = (lane < 4) ? __expf(v3 - mx) : 0.f;
        float s = e0 + e1 + e2 + e3;
#pragma unroll
        for (int off = 16; off >= 1; off >>= 1)
            s += __shfl_xor_sync(0xffffffffu, s, off);
        float inv = 1.f / s;
        float* dst = g_B + g * 1200 + c;
        dst[(lane)      * 12] = e0 * inv;
        dst[(lane + 32) * 12] = e1 * inv;
        dst[(lane + 64) * 12] = e2 * inv;
        if (lane < 4) dst[(lane + 96) * 12] = e3 * inv;
    }

    // ---- A softmax over c, per (d, j, g) ----
    if (t < 128) {
        int g = t & 3, j = (t >> 2) & 3, d = t >> 4;
        float v[8]; float mx = -1e30f;
#pragma unroll
        for (int c = 0; c < 8; ++c) { v[c] = A[c * 128 + d * 16 + j * 4 + g]; mx = fmaxf(mx, v[c]); }
        float s = 0.f;
#pragma unroll
        for (int c = 0; c < 8; ++c) { v[c] = __expf(v[c] - mx); s += v[c]; }
        float inv = 1.f / s;
#pragma unroll
        for (int c = 0; c < 8; ++c) g_T[g * 256 + j * 64 + c * 8 + d] = v[c] * inv;
    } else if (t < 132) {
        int g = t - 128;
        float v[8]; float mx = -1e30f;
#pragma unroll
        for (int c = 0; c < 8; ++c) { v[c] = Pi[c * 4 + g]; mx = fmaxf(mx, v[c]); }
        float s = 0.f;
#pragma unroll
        for (int c = 0; c < 8; ++c) { v[c] = __expf(v[c] - mx); s += v[c]; }
        float inv = 1.f / s;
#pragma unroll
        for (int c = 0; c < 8; ++c) g_Pi[g * 8 + c] = v[c] * inv;
    }

    __syncthreads();

    // ---- leaf-lift table U and LN ----
    for (int job = t; job < 1600; job += 1024) {
        int v = job % 100;
        int j = (job / 100) & 3;
        int g = job / 400;
        float e[8];
#pragma unroll
        for (int c = 0; c < 8; ++c) e[c] = g_B[g * 1200 + v * 12 + c];
        float s = sum8(e);
        float inv = 1.f / s;
        const float* T = &g_T[g * 256 + j * 64];
        float* dst = &g_U[g * 4800 + (j * 100 + v) * 12];
#pragma unroll
        for (int d = 0; d < 8; ++d) {
            float acc = 0.f;
#pragma unroll
            for (int c = 0; c < 8; ++c) acc = fmaf(T[c * 8 + d], e[c], acc);
            dst[d] = acc * inv;
        }
        if (j == 0) g_LN[g * NSYM + v] = __logf(s);
    }
}

// ---------------- K1: levels 8,7,6 (thread per (n6,g)) ----------------
__global__ void __launch_bounds__(512) k_bottom(const int* __restrict__ x) {
    __shared__ __align__(16) float sT[256];
    __shared__ __align__(16) float sB[1200];
    __shared__ __align__(16) float sU[4800];
    __shared__ float sLN[NSYM];
    int g = blockIdx.x >> 6;
    for (int i = threadIdx.x; i < 256;  i += 512) sT[i] = g_T[g * 256 + i];
    for (int i = threadIdx.x; i < 1200; i += 512) sB[i] = g_B[g * 1200 + i];
    for (int i = threadIdx.x; i < 4800; i += 512) sU[i] = g_U[g * 4800 + i];
    if (threadIdx.x < NSYM) sLN[threadIdx.x] = g_LN[g * NSYM + threadIdx.x];
    __syncthreads();

    int n6 = ((blockIdx.x & 63) << 9) + threadIdx.x;

    int v6 = __ldg(&x[OFF6 + n6]);
    int4 x7 = *reinterpret_cast<const int4*>(&x[OFF7 + 4 * n6]);
    const int4* px8 = reinterpret_cast<const int4*>(&x[OFF8 + 16 * n6]);
    int4 xa = px8[0], xb = px8[1], xc = px8[2], xd = px8[3];
    int v7a[4]  = { x7.x, x7.y, x7.z, x7.w };
    int v8a[16] = { xa.x, xa.y, xa.z, xa.w, xb.x, xb.y, xb.z, xb.w,
                    xc.x, xc.y, xc.z, xc.w, xd.x, xd.y, xd.z, xd.w };

    float p6[8]; emload(sB, v6, p6);
    float ell = 0.f;
#pragma unroll 1
    for (int j7 = 0; j7 < 4; ++j7) {
        float p[8]; emload(sB, v7a[j7], p);
#pragma unroll
        for (int j8 = 0; j8 < 4; ++j8) {
            int v = v8a[4 * j7 + j8];
            const float4* u = reinterpret_cast<const float4*>(sU + (j8 * 100 + v) * 12);
            float4 ua = u[0], ub = u[1];
            p[0] *= ua.x; p[1] *= ua.y; p[2] *= ua.z; p[3] *= ua.w;
            p[4] *= ub.x; p[5] *= ub.y; p[6] *= ub.z; p[7] *= ub.w;
            ell += sLN[v];
        }
        float nu  = sum8(p);
        ell      += __logf(nu);
        float inv = __fdividef(1.f, nu);
        float m[8]; matvecS(&sT[j7 * 64], p, m);
#pragma unroll
        for (int d = 0; d < 8; ++d) p6[d] *= m[d] * inv;
    }
    float nu6  = sum8(p6);
    ell       += __logf(nu6);
    float inv6 = __fdividef(1.f, nu6);

    float4* ob = reinterpret_cast<float4*>(&g_beta6[((size_t)g * N6 + n6) * 8]);
    ob[0] = make_float4(p6[0] * inv6, p6[1] * inv6, p6[2] * inv6, p6[3] * inv6);
    ob[1] = make_float4(p6[4] * inv6, p6[5] * inv6, p6[6] * inv6, p6[7] * inv6);
    g_ell6[(size_t)g * N6 + n6] = ell;
}

// ---------------- K2: levels 6->4, warp per (g,n4) ----------------
// group k (8 lanes) = child n5 = 4*n4+k; lane holds state component d
__global__ void __launch_bounds__(256) k_mid64(const int* __restrict__ x) {
    __shared__ __align__(16) float sT[256];
    __shared__ __align__(16) float sB[1200];
    int g = blockIdx.x >> 8;                         // 256 blocks per g
    for (int i = threadIdx.x; i < 256;  i += 256) sT[i] = g_T[g * 256 + i];
    for (int i = threadIdx.x; i < 1200; i += 256) sB[i] = g_B[g * 1200 + i];
    __syncthreads();

    int warp = threadIdx.x >> 5, lane = threadIdx.x & 31;
    int k = lane >> 3, d = lane & 7;
    int n4 = ((blockIdx.x & 255) << 3) + warp;       // 0..2047
    int n5 = 4 * n4 + k;

    // ---- level 6 children into n5 ----
    int v5 = __ldg(&x[OFF5 + n5]);
    float p = sB[v5 * 12 + d];
    float ell = 0.f;
#pragma unroll
    for (int j6 = 0; j6 < 4; ++j6) {
        int n6 = 4 * n5 + j6;
        float b = g_beta6[((size_t)g * N6 + n6) * 8 + d];
        ell += g_ell6[(size_t)g * N6 + n6];
        p *= groupMatvec(&sT[j6 * 64], b, d);
    }
    float nu = groupSum8(p);
    ell += __logf(nu);
    p *= __fdividef(1.f, nu);

    // ---- n5 -> n4 ----
    float m = groupMatvec(&sT[k * 64], p, d);
    // product over the 4 groups + ell sum
    m   *= __shfl_xor_sync(0xffffffffu, m, 8);
    ell += __shfl_xor_sync(0xffffffffu, ell, 8);
    m   *= __shfl_xor_sync(0xffffffffu, m, 16);
    ell += __shfl_xor_sync(0xffffffffu, ell, 16);

    int v4 = __ldg(&x[OFF4 + n4]);
    float p4 = sB[v4 * 12 + d] * m;
    float nu4 = groupSum8(p4);
    ell += __logf(nu4);
    p4 *= __fdividef(1.f, nu4);

    if (k == 0) g_beta4[((size_t)g * N4 + n4) * 8 + d] = p4;
    if (lane == 0) g_ell4[(size_t)g * N4 + n4] = ell;
}

// ---------------- K3: levels 4->2, warp per (g,n2) ----------------
__global__ void __launch_bounds__(256) k_tail42(const int* __restrict__ x) {
    __shared__ __align__(16) float sT[256];
    __shared__ __align__(16) float sB[1200];
    int g = blockIdx.x >> 4;                         // 16 blocks per g
    for (int i = threadIdx.x; i < 256;  i += 256) sT[i] = g_T[g * 256 + i];
    for (int i = threadIdx.x; i < 1200; i += 256) sB[i] = g_B[g * 1200 + i];
    __syncthreads();

    int warp = threadIdx.x >> 5, lane = threadIdx.x & 31;
    int k = lane >> 3, d = lane & 7;
    int n2 = ((blockIdx.x & 15) << 3) + warp;        // 0..127
    int n3 = 4 * n2 + k;

    int v3 = __ldg(&x[OFF3 + n3]);
    float p = sB[v3 * 12 + d];
    float ell = 0.f;
#pragma unroll
    for (int j4 = 0; j4 < 4; ++j4) {
        int n4 = 4 * n3 + j4;
        float b = g_beta4[((size_t)g * N4 + n4) * 8 + d];
        ell += g_ell4[(size_t)g * N4 + n4];
        p *= groupMatvec(&sT[j4 * 64], b, d);
    }
    float nu = groupSum8(p);
    ell += __logf(nu);
    p *= __fdividef(1.f, nu);

    float m = groupMatvec(&sT[k * 64], p, d);
    m   *= __shfl_xor_sync(0xffffffffu, m, 8);
    ell += __shfl_xor_sync(0xffffffffu, ell, 8);
    m   *= __shfl_xor_sync(0xffffffffu, m, 16);
    ell += __shfl_xor_sync(0xffffffffu, ell, 16);

    int v2 = __ldg(&x[OFF2 + n2]);
    float p2 = sB[v2 * 12 + d] * m;
    float nu2 = groupSum8(p2);
    ell += __logf(nu2);
    p2 *= __fdividef(1.f, nu2);

    if (k == 0) g_beta2[((size_t)g * N2 + n2) * 8 + d] = p2;
    if (lane == 0) g_ell2[(size_t)g * N2 + n2] = ell;
}

// ---------------- K4: levels 2->0 + Pi, warp per tree; block per g ----------------
__global__ void __launch_bounds__(256) k_final(const int* __restrict__ x, float* __restrict__ out) {
    __shared__ __align__(16) float sT[256];
    __shared__ __align__(16) float sB[1200];
    int g = blockIdx.x;
    for (int i = threadIdx.x; i < 256;  i += 256) sT[i] = g_T[g * 256 + i];
    for (int i = threadIdx.x; i < 1200; i += 256) sB[i] = g_B[g * 1200 + i];
    __syncthreads();

    int tree = threadIdx.x >> 5, lane = threadIdx.x & 31;
    int k = lane >> 3, d = lane & 7;
    int n1 = 4 * tree + k;

    int v1 = __ldg(&x[OFF1 + n1]);
    float p = sB[v1 * 12 + d];
    float ell = 0.f;
#pragma unroll
    for (int j2 = 0; j2 < 4; ++j2) {
        int n2 = 4 * n1 + j2;
        float b = g_beta2[((size_t)g * N2 + n2) * 8 + d];
        ell += g_ell2[(size_t)g * N2 + n2];
        p *= groupMatvec(&sT[j2 * 64], b, d);
    }
    float nu = groupSum8(p);
    ell += __logf(nu);
    p *= __fdividef(1.f, nu);

    float m = groupMatvec(&sT[k * 64], p, d);
    m   *= __shfl_xor_sync(0xffffffffu, m, 8);
    ell += __shfl_xor_sync(0xffffffffu, ell, 8);
    m   *= __shfl_xor_sync(0xffffffffu, m, 16);
    ell += __shfl_xor_sync(0xffffffffu, ell, 16);

    int v0 = __ldg(&x[OFF0 + tree]);
    float p0 = sB[v0 * 12 + d] * m;
    float nu0 = groupSum8(p0);
    ell += __logf(nu0);
    p0 *= __fdividef(1.f, nu0);

    float z = g_Pi[g * 8 + d] * p0;
    float Z = groupSum8(z);
    if (lane == 0) out[tree * NGEN + g] = __logf(Z) + ell;
}

// ---------------- launcher ----------------
extern "C" void kernel_launch(void* const* d_in, const int* in_sizes, int n_in,
                              void* d_out, int out_size) {
    const int*   x  = nullptr;
    const float* A  = nullptr;
    const float* Bm = nullptr;
    const float* Pi = nullptr;
    for (int i = 0; i < n_in; ++i) {
        switch (in_sizes[i]) {
            case DIMX: x  = (const int*)  d_in[i]; break;
            case 1024: A  = (const float*)d_in[i]; break;
            case 3200: Bm = (const float*)d_in[i]; break;
            case 32:   Pi = (const float*)d_in[i]; break;
            default: break;
        }
    }
    k_prep   <<<   1, 1024>>>(A, Bm, Pi);
    k_bottom <<< 256,  512>>>(x);
    k_mid64  <<<1024,  256>>>(x);
    k_tail42 <<<  64,  256>>>(x);
    k_final  <<<   4,  256>>>(x, (float*)d_out);
}

// round 5
// speedup vs baseline: 3.4027x; 1.4762x over previous
#include <cuda_runtime.h>

// ---------------- problem constants ----------------
#define NGEN  4
#define NSYM  100
// level offsets into x (cumsum of 8*4^l)
#define OFF0 0
#define OFF1 8
#define OFF2 40
#define OFF3 168
#define OFF4 680
#define OFF5 2728
#define OFF6 10920
#define OFF7 43688
#define OFF8 174760
#define DIMX 699048

#define N4 2048

// ---------------- scratch (static device, no allocs) ----------------
__device__ float g_beta4[(size_t)N4 * NGEN * 8];
__device__ float g_ell4 [(size_t)N4 * NGEN];

// ---------------- helpers ----------------
__device__ __forceinline__ void emload(const float* __restrict__ sB, int v, float e[8]) {
    const float4* p = reinterpret_cast<const float4*>(sB + v * 12);
    float4 a = p[0], b = p[1];
    e[0] = a.x; e[1] = a.y; e[2] = a.z; e[3] = a.w;
    e[4] = b.x; e[5] = b.y; e[6] = b.z; e[7] = b.w;
}

// m[d] = sum_c Tj[c*8+d] * r[c]; T tile is 64 floats at sTj (16B aligned)
__device__ __forceinline__ void matvecS(const float* __restrict__ sTj, const float r[8], float m[8]) {
    const float4* T4 = reinterpret_cast<const float4*>(sTj);
#pragma unroll
    for (int c = 0; c < 8; ++c) {
        float4 t0 = T4[2 * c];
        float4 t1 = T4[2 * c + 1];
        float rc = r[c];
        if (c == 0) {
            m[0] = t0.x * rc; m[1] = t0.y * rc; m[2] = t0.z * rc; m[3] = t0.w * rc;
            m[4] = t1.x * rc; m[5] = t1.y * rc; m[6] = t1.z * rc; m[7] = t1.w * rc;
        } else {
            m[0] = fmaf(t0.x, rc, m[0]); m[1] = fmaf(t0.y, rc, m[1]);
            m[2] = fmaf(t0.z, rc, m[2]); m[3] = fmaf(t0.w, rc, m[3]);
            m[4] = fmaf(t1.x, rc, m[4]); m[5] = fmaf(t1.y, rc, m[5]);
            m[6] = fmaf(t1.z, rc, m[6]); m[7] = fmaf(t1.w, rc, m[7]);
        }
    }
}

__device__ __forceinline__ float sum8(const float v[8]) {
    return ((v[0] + v[1]) + (v[2] + v[3])) + ((v[4] + v[5]) + (v[6] + v[7]));
}

__device__ __forceinline__ float groupSum8(float v) {
    v += __shfl_xor_sync(0xffffffffu, v, 4, 8);
    v += __shfl_xor_sync(0xffffffffu, v, 2, 8);
    v += __shfl_xor_sync(0xffffffffu, v, 1, 8);
    return v;
}

// m_d = sum_c sTj[c*8+d] * bhat_c  (bhat distributed over 8-lane group)
__device__ __forceinline__ float groupMatvec(const float* __restrict__ sTj, float bhat, int d) {
    float m = 0.f;
#pragma unroll
    for (int c = 0; c < 8; ++c) {
        float bc = __shfl_sync(0xffffffffu, bhat, c, 8);
        m = fmaf(sTj[c * 8 + d], bc, m);
    }
    return m;
}

// ---- in-block table prep (B softmax for own g; A softmax for own g) ----
// sB: 1200 floats [sym*12 + c]; sT: 288 floats [j*72 + c*8 + d]
__device__ __forceinline__ void prep_tables(int g, int t,
                                            const float* __restrict__ A,
                                            const float* __restrict__ Bm,
                                            float* __restrict__ sB,
                                            float* __restrict__ sT) {
    int w = t >> 5, lane = t & 31;
    if (w < 8) {                 // B softmax: warp per c
        int c = w;
        const float* src = Bm + c * 400 + g;
        float v0 = src[(lane)      * 4];
        float v1 = src[(lane + 32) * 4];
        float v2 = src[(lane + 64) * 4];
        float v3 = (lane < 4) ? src[(lane + 96) * 4] : -1e30f;
        float mx = fmaxf(fmaxf(v0, v1), fmaxf(v2, v3));
#pragma unroll
        for (int off = 16; off >= 1; off >>= 1)
            mx = fmaxf(mx, __shfl_xor_sync(0xffffffffu, mx, off));
        float e0 = __expf(v0 - mx), e1 = __expf(v1 - mx), e2 = __expf(v2 - mx);
        float e3 = (lane < 4) ? __expf(v3 - mx) : 0.f;
        float s = e0 + e1 + e2 + e3;
#pragma unroll
        for (int off = 16; off >= 1; off >>= 1)
            s += __shfl_xor_sync(0xffffffffu, s, off);
        float inv = 1.f / s;
        float* dst = sB + c;
        dst[(lane)      * 12] = e0 * inv;
        dst[(lane + 32) * 12] = e1 * inv;
        dst[(lane + 64) * 12] = e2 * inv;
        if (lane < 4) dst[(lane + 96) * 12] = e3 * inv;
    }
    if (t < 32) {                // A softmax: 32 jobs (j,d)
        int j = t >> 3, d = t & 7;
        float v[8]; float mx = -1e30f;
#pragma unroll
        for (int c = 0; c < 8; ++c) { v[c] = A[c * 128 + d * 16 + j * 4 + g]; mx = fmaxf(mx, v[c]); }
        float s = 0.f;
#pragma unroll
        for (int c = 0; c < 8; ++c) { v[c] = __expf(v[c] - mx); s += v[c]; }
        float inv = 1.f / s;
#pragma unroll
        for (int c = 0; c < 8; ++c) sT[j * 72 + c * 8 + d] = v[c] * inv;
    }
}

// ================ K1: prep + levels 8,7,6 (thread/n6) + 6->4 (warp/n4) ================
__global__ void __launch_bounds__(512) k_lower(const int* __restrict__ x,
                                               const float* __restrict__ A,
                                               const float* __restrict__ Bm) {
    __shared__ __align__(16) float sT[288];          // padded j-stride 72
    __shared__ __align__(16) float sB[1200];
    __shared__ __align__(16) float sU[4800];         // [(j*100+v)*12 + d]
    __shared__ float sLN[NSYM];
    __shared__ float sBeta6[512 * 10];               // padded stride 10
    __shared__ float sEll6[512];

    int g = blockIdx.x >> 6;
    int blk = blockIdx.x & 63;
    int t = threadIdx.x;

    prep_tables(g, t, A, Bm, sB, sT);
    __syncthreads();

    // leaf-lift table for own g: 400 jobs (j, v)
    if (t < 400) {
        int j = t / 100, v = t - 100 * j;
        float e[8];
#pragma unroll
        for (int c = 0; c < 8; ++c) e[c] = sB[v * 12 + c];
        float s = sum8(e);
        float inv = 1.f / s;
        float* dst = &sU[(j * 100 + v) * 12];
#pragma unroll
        for (int d = 0; d < 8; ++d) {
            float acc = 0.f;
#pragma unroll
            for (int c = 0; c < 8; ++c) acc = fmaf(sT[j * 72 + c * 8 + d], e[c], acc);
            dst[d] = acc * inv;
        }
        if (j == 0) sLN[v] = __logf(s);
    }
    __syncthreads();

    // ---- phase A: levels 8,7,6 ; thread per n6 ----
    {
        int n6 = (blk << 9) + t;
        int v6 = __ldg(&x[OFF6 + n6]);
        int4 x7 = *reinterpret_cast<const int4*>(&x[OFF7 + 4 * n6]);
        const int4* px8 = reinterpret_cast<const int4*>(&x[OFF8 + 16 * n6]);
        int4 xa = px8[0], xb = px8[1], xc = px8[2], xd = px8[3];
        int v7a[4]  = { x7.x, x7.y, x7.z, x7.w };
        int v8a[16] = { xa.x, xa.y, xa.z, xa.w, xb.x, xb.y, xb.z, xb.w,
                        xc.x, xc.y, xc.z, xc.w, xd.x, xd.y, xd.z, xd.w };

        float p6[8]; emload(sB, v6, p6);
        float ell = 0.f;
#pragma unroll 1
        for (int j7 = 0; j7 < 4; ++j7) {
            float p[8]; emload(sB, v7a[j7], p);
#pragma unroll
            for (int j8 = 0; j8 < 4; ++j8) {
                int v = v8a[4 * j7 + j8];
                const float4* u = reinterpret_cast<const float4*>(sU + (j8 * 100 + v) * 12);
                float4 ua = u[0], ub = u[1];
                p[0] *= ua.x; p[1] *= ua.y; p[2] *= ua.z; p[3] *= ua.w;
                p[4] *= ub.x; p[5] *= ub.y; p[6] *= ub.z; p[7] *= ub.w;
                ell += sLN[v];
            }
            float nu  = sum8(p);
            ell      += __logf(nu);
            float inv = __fdividef(1.f, nu);
            float m[8]; matvecS(&sT[j7 * 72], p, m);
#pragma unroll
            for (int d = 0; d < 8; ++d) p6[d] *= m[d] * inv;
        }
        float nu6  = sum8(p6);
        ell       += __logf(nu6);
        float inv6 = __fdividef(1.f, nu6);
#pragma unroll
        for (int d = 0; d < 8; ++d) sBeta6[t * 10 + d] = p6[d] * inv6;
        sEll6[t] = ell;
    }
    __syncthreads();

    // ---- phase B: levels 6->5->4 ; warp per n4 (16 warps x 2 iters) ----
    {
        int w = t >> 5, lane = t & 31;
        int k = lane >> 3, d = lane & 7;
#pragma unroll 1
        for (int i = 0; i < 2; ++i) {
            int n4l = w * 2 + i;                 // 0..31
            int n4g = (blk << 5) + n4l;
            int n5g = 4 * n4g + k;

            float p = sB[__ldg(&x[OFF5 + n5g]) * 12 + d];
            float ell = 0.f;
#pragma unroll
            for (int j6 = 0; j6 < 4; ++j6) {
                int n6l = 16 * n4l + 4 * k + j6;
                float b = sBeta6[n6l * 10 + d];
                ell += sEll6[n6l];
                p *= groupMatvec(&sT[j6 * 72], b, d);
            }
            float nu = groupSum8(p);
            ell += __logf(nu);
            p *= __fdividef(1.f, nu);

            float m = groupMatvec(&sT[k * 72], p, d);
            m   *= __shfl_xor_sync(0xffffffffu, m, 8);
            ell += __shfl_xor_sync(0xffffffffu, ell, 8);
            m   *= __shfl_xor_sync(0xffffffffu, m, 16);
            ell += __shfl_xor_sync(0xffffffffu, ell, 16);

            float p4 = sB[__ldg(&x[OFF4 + n4g]) * 12 + d] * m;
            float nu4 = groupSum8(p4);
            ell += __logf(nu4);
            p4 *= __fdividef(1.f, nu4);

            if (k == 0)    g_beta4[((size_t)g * N4 + n4g) * 8 + d] = p4;
            if (lane == 0) g_ell4[(size_t)g * N4 + n4g] = ell;
        }
    }
}

// ================ K2: prep + levels 4->2 (warp/n2) + 2->0 + Pi (warp/tree) ================
// grid 16: block = (g, pair of trees)
__global__ void __launch_bounds__(256) k_upper(const int* __restrict__ x,
                                               const float* __restrict__ A,
                                               const float* __restrict__ Bm,
                                               const float* __restrict__ Pi,
                                               float* __restrict__ out) {
    __shared__ __align__(16) float sT[288];
    __shared__ __align__(16) float sB[1200];
    __shared__ float sBeta2[32 * 10];
    __shared__ float sEll2[32];
    __shared__ float sPi[8];

    int g = blockIdx.x >> 2;
    int pair = blockIdx.x & 3;                 // trees 2*pair, 2*pair+1
    int t = threadIdx.x;

    prep_tables(g, t, A, Bm, sB, sT);
    if (t == 32) {
        float v[8]; float mx = -1e30f;
#pragma unroll
        for (int c = 0; c < 8; ++c) { v[c] = Pi[c * 4 + g]; mx = fmaxf(mx, v[c]); }
        float s = 0.f;
#pragma unroll
        for (int c = 0; c < 8; ++c) { v[c] = __expf(v[c] - mx); s += v[c]; }
        float inv = 1.f / s;
#pragma unroll
        for (int c = 0; c < 8; ++c) sPi[c] = v[c] * inv;
    }
    __syncthreads();

    int w = t >> 5, lane = t & 31;
    int k = lane >> 3, d = lane & 7;

    // ---- stage A: levels 4->3->2 ; warp per n2 (8 warps x 4 iters) ----
#pragma unroll 1
    for (int i = 0; i < 4; ++i) {
        int n2l = w * 4 + i;                   // 0..31
        int n2g = 32 * pair + n2l;
        int n3g = 4 * n2g + k;

        float p = sB[__ldg(&x[OFF3 + n3g]) * 12 + d];
        float ell = 0.f;
#pragma unroll
        for (int j4 = 0; j4 < 4; ++j4) {
            int n4 = 4 * n3g + j4;
            float b = g_beta4[((size_t)g * N4 + n4) * 8 + d];
            ell += g_ell4[(size_t)g * N4 + n4];
            p *= groupMatvec(&sT[j4 * 72], b, d);
        }
        float nu = groupSum8(p);
        ell += __logf(nu);
        p *= __fdividef(1.f, nu);

        float m = groupMatvec(&sT[k * 72], p, d);
        m   *= __shfl_xor_sync(0xffffffffu, m, 8);
        ell += __shfl_xor_sync(0xffffffffu, ell, 8);
        m   *= __shfl_xor_sync(0xffffffffu, m, 16);
        ell += __shfl_xor_sync(0xffffffffu, ell, 16);

        float p2 = sB[__ldg(&x[OFF2 + n2g]) * 12 + d] * m;
        float nu2 = groupSum8(p2);
        ell += __logf(nu2);
        p2 *= __fdividef(1.f, nu2);

        if (k == 0)    sBeta2[n2l * 10 + d] = p2;
        if (lane == 0) sEll2[n2l] = ell;
    }
    __syncthreads();

    // ---- stage B: levels 2->1->0 + Pi ; warp per tree (warps 0,1) ----
    if (w < 2) {
        int tree = 2 * pair + w;
        int n1 = 4 * tree + k;

        float p = sB[__ldg(&x[OFF1 + n1]) * 12 + d];
        float ell = 0.f;
#pragma unroll
        for (int j2 = 0; j2 < 4; ++j2) {
            int n2l = 16 * w + 4 * k + j2;
            float b = sBeta2[n2l * 10 + d];
            ell += sEll2[n2l];
            p *= groupMatvec(&sT[j2 * 72], b, d);
        }
        float nu = groupSum8(p);
        ell += __logf(nu);
        p *= __fdividef(1.f, nu);

        float m = groupMatvec(&sT[k * 72], p, d);
        m   *= __shfl_xor_sync(0xffffffffu, m, 8);
        ell += __shfl_xor_sync(0xffffffffu, ell, 8);
        m   *= __shfl_xor_sync(0xffffffffu, m, 16);
        ell += __shfl_xor_sync(0xffffffffu, ell, 16);

        float p0 = sB[__ldg(&x[OFF0 + tree]) * 12 + d] * m;
        float nu0 = groupSum8(p0);
        ell += __logf(nu0);
        p0 *= __fdividef(1.f, nu0);

        float Z = groupSum8(sPi[d] * p0);
        if (lane == 0) out[tree * NGEN + g] = __logf(Z) + ell;
    }
}

// ---------------- launcher ----------------
extern "C" void kernel_launch(void* const* d_in, const int* in_sizes, int n_in,
                              void* d_out, int out_size) {
    const int*   x  = nullptr;
    const float* A  = nullptr;
    const float* Bm = nullptr;
    const float* Pi = nullptr;
    for (int i = 0; i < n_in; ++i) {
        switch (in_sizes[i]) {
            case DIMX: x  = (const int*)  d_in[i]; break;
            case 1024: A  = (const float*)d_in[i]; break;
            case 3200: Bm = (const float*)d_in[i]; break;
            case 32:   Pi = (const float*)d_in[i]; break;
            default: break;
        }
    }
    k_lower<<<256, 512>>>(x, A, Bm);
    k_upper<<< 16, 256>>>(x, A, Bm, Pi, (float*)d_out);
}

// round 6
// speedup vs baseline: 3.8444x; 1.1298x over previous
#include <cuda_runtime.h>

// ---------------- problem constants ----------------
#define NGEN  4
#define NSYM  100
// level offsets into x (cumsum of 8*4^l)
#define OFF0 0
#define OFF1 8
#define OFF2 40
#define OFF3 168
#define OFF4 680
#define OFF5 2728
#define OFF6 10920
#define OFF7 43688
#define OFF8 174760
#define DIMX 699048

#define N2 128
#define NBLK 256     // total blocks

// ---------------- scratch (static device, no allocs) ----------------
__device__ float g_beta2[(size_t)NGEN * N2 * 8];
__device__ float g_ell2 [(size_t)NGEN * N2];
__device__ unsigned int g_ctr = 0;

// ---------------- helpers ----------------
__device__ __forceinline__ void emload(const float* __restrict__ sB, int v, float e[8]) {
    const float4* p = reinterpret_cast<const float4*>(sB + v * 12);
    float4 a = p[0], b = p[1];
    e[0] = a.x; e[1] = a.y; e[2] = a.z; e[3] = a.w;
    e[4] = b.x; e[5] = b.y; e[6] = b.z; e[7] = b.w;
}

__device__ __forceinline__ void matvecS(const float* __restrict__ sTj, const float r[8], float m[8]) {
    const float4* T4 = reinterpret_cast<const float4*>(sTj);
#pragma unroll
    for (int c = 0; c < 8; ++c) {
        float4 t0 = T4[2 * c];
        float4 t1 = T4[2 * c + 1];
        float rc = r[c];
        if (c == 0) {
            m[0] = t0.x * rc; m[1] = t0.y * rc; m[2] = t0.z * rc; m[3] = t0.w * rc;
            m[4] = t1.x * rc; m[5] = t1.y * rc; m[6] = t1.z * rc; m[7] = t1.w * rc;
        } else {
            m[0] = fmaf(t0.x, rc, m[0]); m[1] = fmaf(t0.y, rc, m[1]);
            m[2] = fmaf(t0.z, rc, m[2]); m[3] = fmaf(t0.w, rc, m[3]);
            m[4] = fmaf(t1.x, rc, m[4]); m[5] = fmaf(t1.y, rc, m[5]);
            m[6] = fmaf(t1.z, rc, m[6]); m[7] = fmaf(t1.w, rc, m[7]);
        }
    }
}

__device__ __forceinline__ float sum8(const float v[8]) {
    return ((v[0] + v[1]) + (v[2] + v[3])) + ((v[4] + v[5]) + (v[6] + v[7]));
}

__device__ __forceinline__ float groupSum8(float v) {
    v += __shfl_xor_sync(0xffffffffu, v, 4, 8);
    v += __shfl_xor_sync(0xffffffffu, v, 2, 8);
    v += __shfl_xor_sync(0xffffffffu, v, 1, 8);
    return v;
}

__device__ __forceinline__ float groupMatvec(const float* __restrict__ sTj, float bhat, int d) {
    float m = 0.f;
#pragma unroll
    for (int c = 0; c < 8; ++c) {
        float bc = __shfl_sync(0xffffffffu, bhat, c, 8);
        m = fmaf(sTj[c * 8 + d], bc, m);
    }
    return m;
}

// B softmax for one (g,c) by one warp -> dst[sym*12 + c] (dst points at table base + c)
__device__ __forceinline__ void bsoftmax_warp(int g, int c, int lane,
                                              const float* __restrict__ Bm,
                                              float* __restrict__ dstBase) {
    const float* src = Bm + c * 400 + g;
    float v0 = src[(lane)      * 4];
    float v1 = src[(lane + 32) * 4];
    float v2 = src[(lane + 64) * 4];
    float v3 = (lane < 4) ? src[(lane + 96) * 4] : -1e30f;
    float mx = fmaxf(fmaxf(v0, v1), fmaxf(v2, v3));
#pragma unroll
    for (int off = 16; off >= 1; off >>= 1)
        mx = fmaxf(mx, __shfl_xor_sync(0xffffffffu, mx, off));
    float e0 = __expf(v0 - mx), e1 = __expf(v1 - mx), e2 = __expf(v2 - mx);
    float e3 = (lane < 4) ? __expf(v3 - mx) : 0.f;
    float s = e0 + e1 + e2 + e3;
#pragma unroll
    for (int off = 16; off >= 1; off >>= 1)
        s += __shfl_xor_sync(0xffffffffu, s, off);
    float inv = 1.f / s;
    float* dst = dstBase + c;
    dst[(lane)      * 12] = e0 * inv;
    dst[(lane + 32) * 12] = e1 * inv;
    dst[(lane + 64) * 12] = e2 * inv;
    if (lane < 4) dst[(lane + 96) * 12] = e3 * inv;
}

// A softmax for one (g,j,d) -> sTdst[j*72 + c*8 + d]
__device__ __forceinline__ void asoftmax_one(int g, int j, int d,
                                             const float* __restrict__ A,
                                             float* __restrict__ sTdst) {
    float v[8]; float mx = -1e30f;
#pragma unroll
    for (int c = 0; c < 8; ++c) { v[c] = A[c * 128 + d * 16 + j * 4 + g]; mx = fmaxf(mx, v[c]); }
    float s = 0.f;
#pragma unroll
    for (int c = 0; c < 8; ++c) { v[c] = __expf(v[c] - mx); s += v[c]; }
    float inv = 1.f / s;
#pragma unroll
    for (int c = 0; c < 8; ++c) sTdst[j * 72 + c * 8 + d] = v[c] * inv;
}

// ================ single fused kernel ================
__global__ void __launch_bounds__(512) k_all(const int* __restrict__ x,
                                             const float* __restrict__ A,
                                             const float* __restrict__ Bm,
                                             const float* __restrict__ Pi,
                                             float* __restrict__ out) {
    __shared__ __align__(16) float sT[288];          // own g: [j*72 + c*8 + d]
    __shared__ __align__(16) float sB[1200];         // own g: [sym*12 + c]
    __shared__ __align__(16) float pool[10532];      // phase-aliased region
    __shared__ unsigned int sLast;

    // pool carving:
    //   phase A : sU   = pool+0    (4800)   [(j*100+v)*12 + d]
    //             sLN  = pool+4800 (100)
    //             sB6  = pool+4900 (5120)   [n6l*10 + d]
    //             sE6  = pool+10020 (512)
    //   phase B : sB4  = pool+0    (320)    [n4l*10 + d]
    //             sE4  = pool+320  (32)     (sB6/sE6 still live: read-only)
    //   tail    : sT2  = pool+0    (1152)   [g*288 + j*72 + c*8 + d]
    //             sB2t = pool+1152 (4800)   [g*1200 + sym*12 + c]
    //             sPi  = pool+5952 (32)
    float* const sU  = pool;
    float* const sLN = pool + 4800;
    float* const sB6 = pool + 4900;
    float* const sE6 = pool + 10020;
    float* const sB4 = pool;
    float* const sE4 = pool + 320;

    int g   = blockIdx.x >> 6;
    int blk = blockIdx.x & 63;
    int t   = threadIdx.x;
    int w = t >> 5, lane = t & 31;
    int k = lane >> 3, d = lane & 7;

    // ---- prep: own g tables ----
    if (w < 8) bsoftmax_warp(g, w, lane, Bm, sB);
    if (t < 32) asoftmax_one(g, t >> 3, t & 7, A, sT);
    __syncthreads();

    // ---- leaf-lift table U and LN for own g ----
    if (t < 400) {
        int j = t / 100, v = t - 100 * j;
        float e[8];
#pragma unroll
        for (int c = 0; c < 8; ++c) e[c] = sB[v * 12 + c];
        float s = sum8(e);
        float inv = 1.f / s;
        float* dst = &sU[(j * 100 + v) * 12];
#pragma unroll
        for (int dd = 0; dd < 8; ++dd) {
            float acc = 0.f;
#pragma unroll
            for (int c = 0; c < 8; ++c) acc = fmaf(sT[j * 72 + c * 8 + dd], e[c], acc);
            dst[dd] = acc * inv;
        }
        if (j == 0) sLN[v] = __logf(s);
    }
    __syncthreads();

    // ---- phase A: levels 8,7,6 ; thread per n6 ----
    {
        int n6 = (blk << 9) + t;
        int v6 = __ldg(&x[OFF6 + n6]);
        int4 x7 = *reinterpret_cast<const int4*>(&x[OFF7 + 4 * n6]);
        const int4* px8 = reinterpret_cast<const int4*>(&x[OFF8 + 16 * n6]);
        int4 xa = px8[0], xb = px8[1], xc = px8[2], xd = px8[3];
        int v7a[4]  = { x7.x, x7.y, x7.z, x7.w };
        int v8a[16] = { xa.x, xa.y, xa.z, xa.w, xb.x, xb.y, xb.z, xb.w,
                        xc.x, xc.y, xc.z, xc.w, xd.x, xd.y, xd.z, xd.w };

        float p6[8]; emload(sB, v6, p6);
        float ell = 0.f;
#pragma unroll 1
        for (int j7 = 0; j7 < 4; ++j7) {
            float p[8]; emload(sB, v7a[j7], p);
#pragma unroll
            for (int j8 = 0; j8 < 4; ++j8) {
                int v = v8a[4 * j7 + j8];
                const float4* u = reinterpret_cast<const float4*>(sU + (j8 * 100 + v) * 12);
                float4 ua = u[0], ub = u[1];
                p[0] *= ua.x; p[1] *= ua.y; p[2] *= ua.z; p[3] *= ua.w;
                p[4] *= ub.x; p[5] *= ub.y; p[6] *= ub.z; p[7] *= ub.w;
                ell += sLN[v];
            }
            float nu  = sum8(p);
            ell      += __logf(nu);
            float inv = __fdividef(1.f, nu);
            float m[8]; matvecS(&sT[j7 * 72], p, m);
#pragma unroll
            for (int dd = 0; dd < 8; ++dd) p6[dd] *= m[dd] * inv;
        }
        float nu6  = sum8(p6);
        ell       += __logf(nu6);
        float inv6 = __fdividef(1.f, nu6);
#pragma unroll
        for (int dd = 0; dd < 8; ++dd) sB6[t * 10 + dd] = p6[dd] * inv6;
        sE6[t] = ell;
    }
    __syncthreads();

    // ---- phase B: levels 6->5->4 ; warp per n4 (16 warps x 2) -> shared sB4 ----
    {
#pragma unroll 1
        for (int i = 0; i < 2; ++i) {
            int n4l = w * 2 + i;                 // 0..31
            int n4g = (blk << 5) + n4l;
            int n5g = 4 * n4g + k;

            float p = sB[__ldg(&x[OFF5 + n5g]) * 12 + d];
            float ell = 0.f;
#pragma unroll
            for (int j6 = 0; j6 < 4; ++j6) {
                int n6l = 16 * n4l + 4 * k + j6;
                float b = sB6[n6l * 10 + d];
                ell += sE6[n6l];
                p *= groupMatvec(&sT[j6 * 72], b, d);
            }
            float nu = groupSum8(p);
            ell += __logf(nu);
            p *= __fdividef(1.f, nu);

            float m = groupMatvec(&sT[k * 72], p, d);
            m   *= __shfl_xor_sync(0xffffffffu, m, 8);
            ell += __shfl_xor_sync(0xffffffffu, ell, 8);
            m   *= __shfl_xor_sync(0xffffffffu, m, 16);
            ell += __shfl_xor_sync(0xffffffffu, ell, 16);

            float p4 = sB[__ldg(&x[OFF4 + n4g]) * 12 + d] * m;
            float nu4 = groupSum8(p4);
            ell += __logf(nu4);
            p4 *= __fdividef(1.f, nu4);

            if (k == 0)    sB4[n4l * 10 + d] = p4;
            if (lane == 0) sE4[n4l] = ell;
        }
    }
    __syncthreads();

    // ---- phase C: levels 4->3->2 ; warps 0,1 (one n2 each) -> gmem beta2 ----
    if (w < 2) {
        int n2l = w;
        int n2g = blk * 2 + n2l;                 // 0..127
        int n3g = 4 * n2g + k;

        float p = sB[__ldg(&x[OFF3 + n3g]) * 12 + d];
        float ell = 0.f;
#pragma unroll
        for (int j4 = 0; j4 < 4; ++j4) {
            int n4l = 16 * n2l + 4 * k + j4;
            float b = sB4[n4l * 10 + d];
            ell += sE4[n4l];
            p *= groupMatvec(&sT[j4 * 72], b, d);
        }
        float nu = groupSum8(p);
        ell += __logf(nu);
        p *= __fdividef(1.f, nu);

        float m = groupMatvec(&sT[k * 72], p, d);
        m   *= __shfl_xor_sync(0xffffffffu, m, 8);
        ell += __shfl_xor_sync(0xffffffffu, ell, 8);
        m   *= __shfl_xor_sync(0xffffffffu, m, 16);
        ell += __shfl_xor_sync(0xffffffffu, ell, 16);

        float p2 = sB[__ldg(&x[OFF2 + n2g]) * 12 + d] * m;
        float nu2 = groupSum8(p2);
        ell += __logf(nu2);
        p2 *= __fdividef(1.f, nu2);

        if (k == 0)    g_beta2[((size_t)g * N2 + n2g) * 8 + d] = p2;
        if (lane == 0) g_ell2[(size_t)g * N2 + n2g] = ell;
    }
    __syncthreads();

    // ---- arrival: last block does the tail ----
    __threadfence();
    if (t == 0) {
        unsigned int prev = atomicAdd(&g_ctr, 1u);
        sLast = (prev == NBLK - 1) ? 1u : 0u;
    }
    __syncthreads();
    if (!sLast) return;

    // ======== tail (single block): levels 2->1->0 + Pi for all (g,tree) ========
    float* const sT2  = pool;            // 4*288
    float* const sB2t = pool + 1152;     // 4*1200
    float* const sPi  = pool + 5952;     // 4*8

    {   // tables for all 4 g
        for (int rep = 0; rep < 2; ++rep) {
            int job = w + 16 * rep;              // 0..31 -> (c,g)
            bsoftmax_warp(job & 3, job >> 2, lane, Bm, sB2t + (job & 3) * 1200);
        }
        if (t < 128) {
            int gg = t >> 5, rem = t & 31;
            asoftmax_one(gg, rem >> 3, rem & 7, A, sT2 + gg * 288);
        } else if (t < 132) {
            int gg = t - 128;
            float v[8]; float mx = -1e30f;
#pragma unroll
            for (int c = 0; c < 8; ++c) { v[c] = Pi[c * 4 + gg]; mx = fmaxf(mx, v[c]); }
            float s = 0.f;
#pragma unroll
            for (int c = 0; c < 8; ++c) { v[c] = __expf(v[c] - mx); s += v[c]; }
            float inv = 1.f / s;
#pragma unroll
            for (int c = 0; c < 8; ++c) sPi[gg * 8 + c] = v[c] * inv;
        }
    }
    __syncthreads();

#pragma unroll 1
    for (int rep = 0; rep < 2; ++rep) {
        int idx = w * 2 + rep;                   // 0..31
        int gg = idx >> 3, tree = idx & 7;
        const float* Bt = sB2t + gg * 1200;
        const float* Tt = sT2 + gg * 288;
        int n1 = 4 * tree + k;

        float p = Bt[__ldg(&x[OFF1 + n1]) * 12 + d];
        float ell = 0.f;
#pragma unroll
        for (int j2 = 0; j2 < 4; ++j2) {
            int n2 = 4 * n1 + j2;
            float b = __ldcg(&g_beta2[((size_t)gg * N2 + n2) * 8 + d]);
            ell += __ldcg(&g_ell2[(size_t)gg * N2 + n2]);
            p *= groupMatvec(&Tt[j2 * 72], b, d);
        }
        float nu = groupSum8(p);
        ell += __logf(nu);
        p *= __fdividef(1.f, nu);

        float m = groupMatvec(&Tt[k * 72], p, d);
        m   *= __shfl_xor_sync(0xffffffffu, m, 8);
        ell += __shfl_xor_sync(0xffffffffu, ell, 8);
        m   *= __shfl_xor_sync(0xffffffffu, m, 16);
        ell += __shfl_xor_sync(0xffffffffu, ell, 16);

        float p0 = Bt[__ldg(&x[OFF0 + tree]) * 12 + d] * m;
        float nu0 = groupSum8(p0);
        ell += __logf(nu0);
        p0 *= __fdividef(1.f, nu0);

        float Z = groupSum8(sPi[gg * 8 + d] * p0);
        if (lane == 0) out[tree * NGEN + gg] = __logf(Z) + ell;
    }

    __syncthreads();
    if (t == 0) g_ctr = 0;      // reset for next graph replay
}

// ---------------- launcher ----------------
extern "C" void kernel_launch(void* const* d_in, const int* in_sizes, int n_in,
                              void* d_out, int out_size) {
    const int*   x  = nullptr;
    const float* A  = nullptr;
    const float* Bm = nullptr;
    const float* Pi = nullptr;
    for (int i = 0; i < n_in; ++i) {
        switch (in_sizes[i]) {
            case DIMX: x  = (const int*)  d_in[i]; break;
            case 1024: A  = (const float*)d_in[i]; break;
            case 3200: Bm = (const float*)d_in[i]; break;
            case 32:   Pi = (const float*)d_in[i]; break;
            default: break;
        }
    }
    k_all<<<NBLK, 512>>>(x, A, Bm, Pi, (float*)d_out);
}